// round 5
// baseline (speedup 1.0000x reference)
#include <cuda_runtime.h>
#include <cuda_bf16.h>
#include <cstdint>
#include <cstring>
#include <math.h>

#define DIN  512
#define DOUT 128
#define MAXN 100000
#define MAXE 3200000

// ---------------- device-global scratch (no runtime allocation) ------------
__device__ __align__(16) float g_xp[(size_t)MAXN * DOUT];      // projected X
__device__ __align__(16) float g_G[DOUT * DOUT];               // gram -> chol L
__device__ __align__(16) __nv_bfloat16 g_wth[DOUT * DIN];      // W_ortho^T hi  [n][k]
__device__ __align__(16) __nv_bfloat16 g_wtl[DOUT * DIN];      // W_ortho^T lo  [n][k]
__device__ int   g_deg[MAXN];
__device__ int   g_rowptr[MAXN + 1];
__device__ int   g_cursor[MAXN];
__device__ int   g_ecol[MAXE];
__device__ float g_eval[MAXE];

__device__ __forceinline__ uint32_t pack_bf16(__nv_bfloat16 a, __nv_bfloat16 b) {
    __nv_bfloat162 t(a, b);
    uint32_t r; memcpy(&r, &t, 4); return r;
}

// warp-level bf16 MMA (sm_80+; compiles on plain sm_100 target)
__device__ __forceinline__ void mma16816(float* d, const uint32_t* a, const uint32_t* b) {
    asm volatile("mma.sync.aligned.m16n8k16.row.col.f32.bf16.bf16.f32 "
        "{%0,%1,%2,%3}, {%4,%5,%6,%7}, {%8,%9}, {%0,%1,%2,%3};"
        : "+f"(d[0]), "+f"(d[1]), "+f"(d[2]), "+f"(d[3])
        : "r"(a[0]), "r"(a[1]), "r"(a[2]), "r"(a[3]), "r"(b[0]), "r"(b[1]));
}

// ---------------- ortho-norm chain ------------------------------------------
// G = W^T W + 1e-4 I.  W: [512, 128] row-major. Block i computes row i of G.
__global__ void k_gram(const float* __restrict__ W) {
    __shared__ float col[DIN];
    int i = blockIdx.x, j = threadIdx.x;
    for (int k = j; k < DIN; k += DOUT) col[k] = W[k * DOUT + i];
    __syncthreads();
    float acc = 0.f;
    #pragma unroll 8
    for (int k = 0; k < DIN; k++) acc = fmaf(col[k], W[k * DOUT + j], acc);
    g_G[i * DOUT + j] = acc + (i == j ? 1e-4f : 0.f);
}

// In-place lower Cholesky of g_G. One block, 128 threads (row per thread).
__global__ void k_chol() {
    extern __shared__ char s_raw[];
    float* s = (float*)s_raw;
    int t = threadIdx.x;
    for (int idx = t; idx < DOUT * DOUT; idx += DOUT) s[idx] = g_G[idx];
    __syncthreads();
    for (int k = 0; k < DOUT; k++) {
        if (t == k) s[k * DOUT + k] = sqrtf(s[k * DOUT + k]);
        __syncthreads();
        float dk = s[k * DOUT + k];
        if (t > k) s[t * DOUT + k] /= dk;
        __syncthreads();
        if (t > k) {
            float lik = s[t * DOUT + k];
            for (int j = k + 1; j <= t; j++) s[t * DOUT + j] -= lik * s[j * DOUT + k];
        }
        __syncthreads();
    }
    for (int idx = t; idx < DOUT * DOUT; idx += DOUT) g_G[idx] = s[idx];
}

// W_ortho row r solves L y = W[r,:]^T (forward substitution); store y^T as
// bf16 hi/lo into g_wth/g_wtl at [j][r]  (W_ortho^T: n-major, k-contiguous-ish).
__global__ void __launch_bounds__(128) k_ortho(const float* __restrict__ W) {
    extern __shared__ char s_raw[];
    float* Ls = (float*)s_raw;                // 128*128 floats
    float* ys = Ls + DOUT * DOUT;             // [j][thread], 128*128 floats
    int t = threadIdx.x;
    for (int idx = t; idx < DOUT * DOUT; idx += 128) Ls[idx] = g_G[idx];
    __syncthreads();
    int r = blockIdx.x * 128 + t;             // 0..511  (k index)
    const float* wr = W + (size_t)r * DOUT;
    for (int j = 0; j < DOUT; j++) {
        float sv = wr[j];
        for (int k = 0; k < j; k++) sv = fmaf(-Ls[j * DOUT + k], ys[k * 128 + t], sv);
        sv /= Ls[j * DOUT + j];
        ys[j * 128 + t] = sv;
        __nv_bfloat16 h = __float2bfloat16_rn(sv);
        float rem = sv - __bfloat162float(h);
        g_wth[j * DIN + r] = h;               // [n=j][k=r]
        g_wtl[j * DIN + r] = __float2bfloat16_rn(rem);
    }
}

// ---------------- GEMM: Xp = X @ W_ortho  (mma.sync bf16 hi/lo split) -------
// CTA: 256 thr (8 warps), M=128, N=128, K chunks of 32, double-buffered smem.
// smem chunk layout per stage: Ah, Al, Bh, Bl each 128 rows x 80 bytes (32 bf16
// + 16B pad to kill bank conflicts on fragment loads).
static constexpr int ST_ROW  = 80;                  // bytes per smem row
static constexpr int TILE_B  = 128 * ST_ROW;        // 10240
static constexpr int STAGE_B = 4 * TILE_B;          // 40960
static constexpr int GEMM_SMEM = 2 * STAGE_B;       // 81920

__global__ void __launch_bounds__(256)
k_gemm(const float* __restrict__ X, int nn) {
    extern __shared__ char smem[];
    int tid  = threadIdx.x;
    int lane = tid & 31;
    int wid  = tid >> 5;
    int warpm = wid & 3;          // 4 tiles of 32 rows
    int warpn = wid >> 2;         // 2 tiles of 64 cols
    int qrow = lane >> 2;         // 0..7
    int qk   = (lane & 3) * 4;    // byte offset of the 2-bf16 pair within k16
    int m0 = blockIdx.x * 128;

    float d[2][8][4];
    #pragma unroll
    for (int mf = 0; mf < 2; mf++)
        #pragma unroll
        for (int nf = 0; nf < 8; nf++)
            #pragma unroll
            for (int q = 0; q < 4; q++) d[mf][nf][q] = 0.f;

    // per-thread staging slots: idx = tid + t*256; row = idx>>3 (0..127),
    // kq = (idx&7)*4 (0..28)  -> covers 128 rows x 32 k (fp32 A, bf16 B).
    int srow[4], skq[4];
    #pragma unroll
    for (int t = 0; t < 4; t++) {
        int idx = tid + t * 256;
        srow[t] = idx >> 3;
        skq[t]  = (idx & 7) << 2;
    }

    // prologue: load chunk 0 into stage 0
    {
        char* st = smem;
        #pragma unroll
        for (int t = 0; t < 4; t++) {
            int row = srow[t], kq = skq[t];
            int m = m0 + row;
            float4 xv = make_float4(0.f, 0.f, 0.f, 0.f);
            if (m < nn) xv = *(const float4*)(X + (size_t)m * DIN + kq);
            __nv_bfloat16 h0 = __float2bfloat16_rn(xv.x), h1 = __float2bfloat16_rn(xv.y);
            __nv_bfloat16 h2 = __float2bfloat16_rn(xv.z), h3 = __float2bfloat16_rn(xv.w);
            uint2 hv; hv.x = pack_bf16(h0, h1); hv.y = pack_bf16(h2, h3);
            uint2 lv;
            lv.x = pack_bf16(__float2bfloat16_rn(xv.x - __bfloat162float(h0)),
                             __float2bfloat16_rn(xv.y - __bfloat162float(h1)));
            lv.y = pack_bf16(__float2bfloat16_rn(xv.z - __bfloat162float(h2)),
                             __float2bfloat16_rn(xv.w - __bfloat162float(h3)));
            int off = row * ST_ROW + kq * 2;
            *(uint2*)(st + off)              = hv;
            *(uint2*)(st + TILE_B + off)     = lv;
            *(uint2*)(st + 2 * TILE_B + off) = *(const uint2*)(g_wth + (size_t)row * DIN + kq);
            *(uint2*)(st + 3 * TILE_B + off) = *(const uint2*)(g_wtl + (size_t)row * DIN + kq);
        }
    }
    __syncthreads();

    #pragma unroll 1
    for (int c = 0; c < 16; c++) {
        int s = c & 1;
        // ---- issue global loads for chunk c+1 (latency hidden by compute) --
        float4 areg[4]; uint2 bh[4], bl[4];
        if (c < 15) {
            int koff = (c + 1) * 32;
            #pragma unroll
            for (int t = 0; t < 4; t++) {
                int row = srow[t], kq = skq[t];
                int m = m0 + row;
                areg[t] = make_float4(0.f, 0.f, 0.f, 0.f);
                if (m < nn) areg[t] = *(const float4*)(X + (size_t)m * DIN + koff + kq);
                bh[t] = *(const uint2*)(g_wth + (size_t)row * DIN + koff + kq);
                bl[t] = *(const uint2*)(g_wtl + (size_t)row * DIN + koff + kq);
            }
        }

        // ---- compute on stage s ----
        const char* Ah = smem + s * STAGE_B;
        const char* Al = Ah + TILE_B;
        const char* Bh = Ah + 2 * TILE_B;
        const char* Bl = Ah + 3 * TILE_B;
        #pragma unroll
        for (int ks = 0; ks < 2; ks++) {
            uint32_t ahf[2][4], alf[2][4];
            #pragma unroll
            for (int mf = 0; mf < 2; mf++) {
                int byt = (warpm * 32 + mf * 16 + qrow) * ST_ROW + ks * 32 + qk;
                ahf[mf][0] = *(const uint32_t*)(Ah + byt);
                ahf[mf][1] = *(const uint32_t*)(Ah + byt + 8 * ST_ROW);
                ahf[mf][2] = *(const uint32_t*)(Ah + byt + 16);
                ahf[mf][3] = *(const uint32_t*)(Ah + byt + 8 * ST_ROW + 16);
                alf[mf][0] = *(const uint32_t*)(Al + byt);
                alf[mf][1] = *(const uint32_t*)(Al + byt + 8 * ST_ROW);
                alf[mf][2] = *(const uint32_t*)(Al + byt + 16);
                alf[mf][3] = *(const uint32_t*)(Al + byt + 8 * ST_ROW + 16);
            }
            #pragma unroll
            for (int nf = 0; nf < 8; nf++) {
                int byt = (warpn * 64 + nf * 8 + qrow) * ST_ROW + ks * 32 + qk;
                uint32_t bhf[2], blf[2];
                bhf[0] = *(const uint32_t*)(Bh + byt);
                bhf[1] = *(const uint32_t*)(Bh + byt + 16);
                blf[0] = *(const uint32_t*)(Bl + byt);
                blf[1] = *(const uint32_t*)(Bl + byt + 16);
                #pragma unroll
                for (int mf = 0; mf < 2; mf++) {
                    mma16816(d[mf][nf], ahf[mf], bhf);
                    mma16816(d[mf][nf], ahf[mf], blf);
                    mma16816(d[mf][nf], alf[mf], bhf);
                }
            }
        }

        // ---- store staged chunk c+1 into stage s^1 ----
        if (c < 15) {
            char* st = smem + (s ^ 1) * STAGE_B;
            #pragma unroll
            for (int t = 0; t < 4; t++) {
                int row = srow[t], kq = skq[t];
                float4 xv = areg[t];
                __nv_bfloat16 h0 = __float2bfloat16_rn(xv.x), h1 = __float2bfloat16_rn(xv.y);
                __nv_bfloat16 h2 = __float2bfloat16_rn(xv.z), h3 = __float2bfloat16_rn(xv.w);
                uint2 hv; hv.x = pack_bf16(h0, h1); hv.y = pack_bf16(h2, h3);
                uint2 lv;
                lv.x = pack_bf16(__float2bfloat16_rn(xv.x - __bfloat162float(h0)),
                                 __float2bfloat16_rn(xv.y - __bfloat162float(h1)));
                lv.y = pack_bf16(__float2bfloat16_rn(xv.z - __bfloat162float(h2)),
                                 __float2bfloat16_rn(xv.w - __bfloat162float(h3)));
                int off = row * ST_ROW + kq * 2;
                *(uint2*)(st + off)              = hv;
                *(uint2*)(st + TILE_B + off)     = lv;
                *(uint2*)(st + 2 * TILE_B + off) = bh[t];
                *(uint2*)(st + 3 * TILE_B + off) = bl[t];
            }
        }
        __syncthreads();
    }

    // ---- epilogue: write Xp ----
    #pragma unroll
    for (int mf = 0; mf < 2; mf++) {
        int r0 = m0 + warpm * 32 + mf * 16 + qrow;
        #pragma unroll
        for (int nf = 0; nf < 8; nf++) {
            int col = warpn * 64 + nf * 8 + (lane & 3) * 2;
            if (r0 < nn) {
                float2 v0 = make_float2(d[mf][nf][0], d[mf][nf][1]);
                *(float2*)(g_xp + (size_t)r0 * DOUT + col) = v0;
            }
            if (r0 + 8 < nn) {
                float2 v1 = make_float2(d[mf][nf][2], d[mf][nf][3]);
                *(float2*)(g_xp + (size_t)(r0 + 8) * DOUT + col) = v1;
            }
        }
    }
}

// ---------------- CSR build --------------------------------------------------
__global__ void k_zero(int n) {
    int i = blockIdx.x * blockDim.x + threadIdx.x;
    if (i < n) g_deg[i] = 0;
}

__global__ void k_hist(const int* __restrict__ rows, int ne) {
    int e = blockIdx.x * blockDim.x + threadIdx.x;
    if (e < ne) atomicAdd(&g_deg[rows[e]], 1);
}

// single-block exclusive scan of g_deg -> g_rowptr; also zero g_cursor
__global__ void __launch_bounds__(1024) k_scan(int n) {
    __shared__ int part[1024];
    int t = threadIdx.x;
    int per = (n + 1023) / 1024;
    int start = t * per;
    int end = min(start + per, n);
    int sum = 0;
    for (int i = start; i < end; i++) sum += g_deg[i];
    part[t] = sum;
    __syncthreads();
    for (int ofs = 1; ofs < 1024; ofs <<= 1) {
        int v = (t >= ofs) ? part[t - ofs] : 0;
        __syncthreads();
        part[t] += v;
        __syncthreads();
    }
    int run = (t == 0) ? 0 : part[t - 1];
    for (int i = start; i < end; i++) {
        int dg = g_deg[i];
        g_rowptr[i] = run;
        g_cursor[i] = 0;
        run += dg;
    }
    if (end == n && start <= n) g_rowptr[n] = run;
}

__global__ void k_scatter(const int* __restrict__ rows, const int* __restrict__ cols,
                          const float* __restrict__ vals, int ne) {
    int e = blockIdx.x * blockDim.x + threadIdx.x;
    if (e >= ne) return;
    int dst = rows[e];
    int pos = g_rowptr[dst] + atomicAdd(&g_cursor[dst], 1);
    g_ecol[pos] = cols[e];
    g_eval[pos] = vals[e];
}

// ---------------- SpMM + tanh: warp per destination row ---------------------
__global__ void __launch_bounds__(256) k_spmm(float* __restrict__ out, int n) {
    int warp = (blockIdx.x * blockDim.x + threadIdx.x) >> 5;
    int lane = threadIdx.x & 31;
    if (warp >= n) return;
    int beg = g_rowptr[warp];
    int end = g_rowptr[warp + 1];
    float4 acc = make_float4(0.f, 0.f, 0.f, 0.f);
    for (int b = beg; b < end; b += 32) {
        int idx = b + lane;
        int cc = 0; float vv = 0.f;
        if (idx < end) { cc = g_ecol[idx]; vv = g_eval[idx]; }
        int cnt = min(32, end - b);
        for (int j = 0; j < cnt; j++) {
            int   cj = __shfl_sync(0xffffffffu, cc, j);
            float vj = __shfl_sync(0xffffffffu, vv, j);
            const float4 xp = *(const float4*)(g_xp + (size_t)cj * DOUT + lane * 4);
            acc.x = fmaf(vj, xp.x, acc.x);
            acc.y = fmaf(vj, xp.y, acc.y);
            acc.z = fmaf(vj, xp.z, acc.z);
            acc.w = fmaf(vj, xp.w, acc.w);
        }
    }
    float4 o;
    o.x = tanhf(acc.x); o.y = tanhf(acc.y);
    o.z = tanhf(acc.z); o.w = tanhf(acc.w);
    *(float4*)(out + (size_t)warp * DOUT + lane * 4) = o;
}

// ---------------- launch -----------------------------------------------------
extern "C" void kernel_launch(void* const* d_in, const int* in_sizes, int n_in,
                              void* d_out, int out_size) {
    const float* X    = (const float*)d_in[0];   // [N, 512]
    const float* W    = (const float*)d_in[1];   // [512, 128]
    const float* vals = (const float*)d_in[2];   // [E]
    const int*   rows = (const int*)d_in[3];     // [E]
    const int*   cols = (const int*)d_in[4];     // [E]
    float* out = (float*)d_out;

    int nn = in_sizes[0] / DIN;
    int ne = in_sizes[2];

    cudaFuncSetAttribute(k_chol,  cudaFuncAttributeMaxDynamicSharedMemorySize, 65536);
    cudaFuncSetAttribute(k_ortho, cudaFuncAttributeMaxDynamicSharedMemorySize, 131072);
    cudaFuncSetAttribute(k_gemm,  cudaFuncAttributeMaxDynamicSharedMemorySize, GEMM_SMEM);

    // ortho-norm chain
    k_gram<<<DOUT, DOUT>>>(W);
    k_chol<<<1, DOUT, 65536>>>();
    k_ortho<<<DIN / 128, 128, 131072>>>(W);

    // CSR build
    k_zero<<<(nn + 255) / 256, 256>>>(nn);
    k_hist<<<(ne + 255) / 256, 256>>>(rows, ne);
    k_scan<<<1, 1024>>>(nn);
    k_scatter<<<(ne + 255) / 256, 256>>>(rows, cols, vals, ne);

    // dense projection on tensor cores (mma.sync bf16 split)
    k_gemm<<<(nn + 127) / 128, 256, GEMM_SMEM>>>(X, nn);

    // SpMM + tanh
    k_spmm<<<(nn * 32 + 255) / 256, 256>>>(out, nn);
}

// round 6
// speedup vs baseline: 1.0920x; 1.0920x over previous
#include <cuda_runtime.h>
#include <cuda_bf16.h>
#include <cstdint>
#include <cstring>
#include <math.h>

#define DIN  512
#define DOUT 128
#define MAXN 100000
#define MAXE 3200000

// ---------------- device-global scratch (no runtime allocation) ------------
__device__ __align__(16) float g_xp[(size_t)MAXN * DOUT];      // projected X
__device__ __align__(16) float g_G[DOUT * DOUT];               // gram -> chol L
__device__ __align__(16) __nv_bfloat16 g_wth[DOUT * DIN];      // W_ortho^T hi  [n][k]
__device__ __align__(16) __nv_bfloat16 g_wtl[DOUT * DIN];      // W_ortho^T lo  [n][k]
__device__ int   g_deg[MAXN];
__device__ int   g_rowptr[MAXN + 1];
__device__ int   g_cursor[MAXN];
__device__ __align__(8) int2 g_edge[MAXE];                     // .x=col .y=val bits

__device__ __forceinline__ uint32_t pack_bf16(__nv_bfloat16 a, __nv_bfloat16 b) {
    __nv_bfloat162 t(a, b);
    uint32_t r; memcpy(&r, &t, 4); return r;
}

__device__ __forceinline__ uint32_t smem_u32(const void* p) {
    return (uint32_t)__cvta_generic_to_shared(p);
}

// async 16B copy, L1-bypass
__device__ __forceinline__ void cp16(uint32_t s, const void* g) {
    asm volatile("cp.async.cg.shared.global [%0], [%1], 16;" :: "r"(s), "l"(g));
}
#define CP_COMMIT() asm volatile("cp.async.commit_group;")
#define CP_WAIT0()  asm volatile("cp.async.wait_group 0;")

// warp-level bf16 MMA (sm_80+; compiles on plain sm_100 target)
__device__ __forceinline__ void mma16816(float* d, const uint32_t* a, const uint32_t* b) {
    asm volatile("mma.sync.aligned.m16n8k16.row.col.f32.bf16.bf16.f32 "
        "{%0,%1,%2,%3}, {%4,%5,%6,%7}, {%8,%9}, {%0,%1,%2,%3};"
        : "+f"(d[0]), "+f"(d[1]), "+f"(d[2]), "+f"(d[3])
        : "r"(a[0]), "r"(a[1]), "r"(a[2]), "r"(a[3]), "r"(b[0]), "r"(b[1]));
}

// ---------------- kA: Gram matrix + zero deg/cursor --------------------------
// blocks [0, 128): G = W^T W + 1e-4 I (block i = row i of G)
// blocks [128, ..): zero g_deg (first n idx) and g_cursor (next n idx)
__global__ void __launch_bounds__(128) kA(const float* __restrict__ W, int n) {
    if (blockIdx.x < DOUT) {
        __shared__ float col[DIN];
        int i = blockIdx.x, j = threadIdx.x;
        for (int k = j; k < DIN; k += DOUT) col[k] = W[k * DOUT + i];
        __syncthreads();
        float acc = 0.f;
        #pragma unroll 8
        for (int k = 0; k < DIN; k++) acc = fmaf(col[k], W[k * DOUT + j], acc);
        g_G[i * DOUT + j] = acc + (i == j ? 1e-4f : 0.f);
    } else {
        int i = (blockIdx.x - DOUT) * 128 + threadIdx.x;
        if (i < n) g_deg[i] = 0;
        else if (i < 2 * n) g_cursor[i - n] = 0;
    }
}

// In-place lower Cholesky of g_G. One block, 128 threads (row per thread).
__global__ void k_chol() {
    extern __shared__ char s_raw[];
    float* s = (float*)s_raw;
    int t = threadIdx.x;
    for (int idx = t; idx < DOUT * DOUT; idx += DOUT) s[idx] = g_G[idx];
    __syncthreads();
    for (int k = 0; k < DOUT; k++) {
        if (t == k) s[k * DOUT + k] = sqrtf(s[k * DOUT + k]);
        __syncthreads();
        float dk = s[k * DOUT + k];
        if (t > k) s[t * DOUT + k] /= dk;
        __syncthreads();
        if (t > k) {
            float lik = s[t * DOUT + k];
            for (int j = k + 1; j <= t; j++) s[t * DOUT + j] -= lik * s[j * DOUT + k];
        }
        __syncthreads();
    }
    for (int idx = t; idx < DOUT * DOUT; idx += DOUT) g_G[idx] = s[idx];
}

// W_ortho row r solves L y = W[r,:]^T; store y^T bf16 hi/lo at [n=j][k=r].
__global__ void __launch_bounds__(128) k_ortho(const float* __restrict__ W) {
    extern __shared__ char s_raw[];
    float* Ls = (float*)s_raw;                // 128*128 floats
    float* ys = Ls + DOUT * DOUT;             // [j][thread]
    int t = threadIdx.x;
    for (int idx = t; idx < DOUT * DOUT; idx += 128) Ls[idx] = g_G[idx];
    __syncthreads();
    int r = blockIdx.x * 128 + t;             // 0..511 (k index)
    const float* wr = W + (size_t)r * DOUT;
    for (int j = 0; j < DOUT; j++) {
        float sv = wr[j];
        for (int k = 0; k < j; k++) sv = fmaf(-Ls[j * DOUT + k], ys[k * 128 + t], sv);
        sv /= Ls[j * DOUT + j];
        ys[j * 128 + t] = sv;
        __nv_bfloat16 h = __float2bfloat16_rn(sv);
        float rem = sv - __bfloat162float(h);
        g_wth[j * DIN + r] = h;
        g_wtl[j * DIN + r] = __float2bfloat16_rn(rem);
    }
}

// ---------------- GEMM: Xp = X @ W_ortho  (mma.sync bf16 hi/lo split) -------
// CTA: 256 thr (8 warps), M=128, N=128, K chunks of 32, double-buffered smem.
// smem rows are 80 B (64 B data + 16 B pad) to avoid bank conflicts.
static constexpr int ST_ROW  = 80;
static constexpr int TILE_B  = 128 * ST_ROW;        // 10240
static constexpr int STAGE_B = 4 * TILE_B;          // 40960 (Ah, Al, Bh, Bl)
static constexpr int GEMM_SMEM = 2 * STAGE_B;       // 81920

__global__ void __launch_bounds__(256)
k_gemm(const float* __restrict__ X, int nn) {
    extern __shared__ char smem[];
    uint32_t sm0 = smem_u32(smem);
    int tid  = threadIdx.x;
    int lane = tid & 31;
    int wid  = tid >> 5;
    int warpm = wid & 3;          // 4 tiles of 32 rows
    int warpn = wid >> 2;         // 2 tiles of 64 cols
    int qrow = lane >> 2;         // 0..7
    int qk   = (lane & 3) * 4;    // byte offset within k16
    int m0 = blockIdx.x * 128;

    float d[2][8][4];
    #pragma unroll
    for (int mf = 0; mf < 2; mf++)
        #pragma unroll
        for (int nf = 0; nf < 8; nf++)
            #pragma unroll
            for (int q = 0; q < 4; q++) d[mf][nf][q] = 0.f;

    // A staging slots: idx = tid + t*256; row = idx>>3, kq = (idx&7)*4
    int srow[4], skq[4];
    #pragma unroll
    for (int t = 0; t < 4; t++) {
        int idx = tid + t * 256;
        srow[t] = idx >> 3;
        skq[t]  = (idx & 7) << 2;
    }
    // B cp.async slots: idx = tid + t*256; row = idx>>2, q = idx&3 (16B units)
    int brow[2], bq[2];
    #pragma unroll
    for (int t = 0; t < 2; t++) {
        int idx = tid + t * 256;
        brow[t] = idx >> 2;
        bq[t]   = (idx & 3) * 16;
    }

    // ---- prologue: chunk 0 ----
    {
        uint32_t sBh = sm0 + 2 * TILE_B, sBl = sm0 + 3 * TILE_B;
        #pragma unroll
        for (int t = 0; t < 2; t++) {
            int off = brow[t] * ST_ROW + bq[t];
            cp16(sBh + off, (const char*)(g_wth + (size_t)brow[t] * DIN) + bq[t]);
            cp16(sBl + off, (const char*)(g_wtl + (size_t)brow[t] * DIN) + bq[t]);
        }
        CP_COMMIT();
        char* st = smem;
        #pragma unroll
        for (int t = 0; t < 4; t++) {
            int row = srow[t], kq = skq[t];
            int m = m0 + row;
            float4 xv = make_float4(0.f, 0.f, 0.f, 0.f);
            if (m < nn) xv = *(const float4*)(X + (size_t)m * DIN + kq);
            __nv_bfloat16 h0 = __float2bfloat16_rn(xv.x), h1 = __float2bfloat16_rn(xv.y);
            __nv_bfloat16 h2 = __float2bfloat16_rn(xv.z), h3 = __float2bfloat16_rn(xv.w);
            uint2 hv; hv.x = pack_bf16(h0, h1); hv.y = pack_bf16(h2, h3);
            uint2 lv;
            lv.x = pack_bf16(__float2bfloat16_rn(xv.x - __bfloat162float(h0)),
                             __float2bfloat16_rn(xv.y - __bfloat162float(h1)));
            lv.y = pack_bf16(__float2bfloat16_rn(xv.z - __bfloat162float(h2)),
                             __float2bfloat16_rn(xv.w - __bfloat162float(h3)));
            int off = row * ST_ROW + kq * 2;
            *(uint2*)(st + off)          = hv;
            *(uint2*)(st + TILE_B + off) = lv;
        }
        CP_WAIT0();
    }
    __syncthreads();

    #pragma unroll 1
    for (int c = 0; c < 16; c++) {
        int s = c & 1;
        float4 areg[4];
        if (c < 15) {
            int koff = (c + 1) * 32;
            // B for chunk c+1 via cp.async into stage s^1
            uint32_t nst = sm0 + (uint32_t)(s ^ 1) * STAGE_B;
            #pragma unroll
            for (int t = 0; t < 2; t++) {
                int off = brow[t] * ST_ROW + bq[t];
                const char* gh = (const char*)(g_wth + (size_t)brow[t] * DIN + koff) + bq[t];
                const char* gl = (const char*)(g_wtl + (size_t)brow[t] * DIN + koff) + bq[t];
                cp16(nst + 2 * TILE_B + off, gh);
                cp16(nst + 3 * TILE_B + off, gl);
            }
            CP_COMMIT();
            // A for chunk c+1 into registers
            #pragma unroll
            for (int t = 0; t < 4; t++) {
                int m = m0 + srow[t];
                areg[t] = make_float4(0.f, 0.f, 0.f, 0.f);
                if (m < nn) areg[t] = *(const float4*)(X + (size_t)m * DIN + koff + skq[t]);
            }
        }

        // ---- compute on stage s ----
        const char* Ah = smem + s * STAGE_B;
        const char* Al = Ah + TILE_B;
        const char* Bh = Ah + 2 * TILE_B;
        const char* Bl = Ah + 3 * TILE_B;
        #pragma unroll
        for (int ks = 0; ks < 2; ks++) {
            uint32_t ahf[2][4], alf[2][4];
            #pragma unroll
            for (int mf = 0; mf < 2; mf++) {
                int byt = (warpm * 32 + mf * 16 + qrow) * ST_ROW + ks * 32 + qk;
                ahf[mf][0] = *(const uint32_t*)(Ah + byt);
                ahf[mf][1] = *(const uint32_t*)(Ah + byt + 8 * ST_ROW);
                ahf[mf][2] = *(const uint32_t*)(Ah + byt + 16);
                ahf[mf][3] = *(const uint32_t*)(Ah + byt + 8 * ST_ROW + 16);
                alf[mf][0] = *(const uint32_t*)(Al + byt);
                alf[mf][1] = *(const uint32_t*)(Al + byt + 8 * ST_ROW);
                alf[mf][2] = *(const uint32_t*)(Al + byt + 16);
                alf[mf][3] = *(const uint32_t*)(Al + byt + 8 * ST_ROW + 16);
            }
            #pragma unroll
            for (int nf = 0; nf < 8; nf++) {
                int byt = (warpn * 64 + nf * 8 + qrow) * ST_ROW + ks * 32 + qk;
                uint32_t bhf[2], blf[2];
                bhf[0] = *(const uint32_t*)(Bh + byt);
                bhf[1] = *(const uint32_t*)(Bh + byt + 16);
                blf[0] = *(const uint32_t*)(Bl + byt);
                blf[1] = *(const uint32_t*)(Bl + byt + 16);
                #pragma unroll
                for (int mf = 0; mf < 2; mf++) {
                    mma16816(d[mf][nf], ahf[mf], bhf);
                    mma16816(d[mf][nf], ahf[mf], blf);
                    mma16816(d[mf][nf], alf[mf], bhf);
                }
            }
        }

        if (c < 15) {
            // store staged A chunk c+1 into stage s^1
            char* st = smem + (s ^ 1) * STAGE_B;
            #pragma unroll
            for (int t = 0; t < 4; t++) {
                int row = srow[t], kq = skq[t];
                float4 xv = areg[t];
                __nv_bfloat16 h0 = __float2bfloat16_rn(xv.x), h1 = __float2bfloat16_rn(xv.y);
                __nv_bfloat16 h2 = __float2bfloat16_rn(xv.z), h3 = __float2bfloat16_rn(xv.w);
                uint2 hv; hv.x = pack_bf16(h0, h1); hv.y = pack_bf16(h2, h3);
                uint2 lv;
                lv.x = pack_bf16(__float2bfloat16_rn(xv.x - __bfloat162float(h0)),
                                 __float2bfloat16_rn(xv.y - __bfloat162float(h1)));
                lv.y = pack_bf16(__float2bfloat16_rn(xv.z - __bfloat162float(h2)),
                                 __float2bfloat16_rn(xv.w - __bfloat162float(h3)));
                int off = row * ST_ROW + kq * 2;
                *(uint2*)(st + off)          = hv;
                *(uint2*)(st + TILE_B + off) = lv;
            }
        }
        CP_WAIT0();
        __syncthreads();
    }

    // ---- epilogue: write Xp ----
    #pragma unroll
    for (int mf = 0; mf < 2; mf++) {
        int r0 = m0 + warpm * 32 + mf * 16 + qrow;
        #pragma unroll
        for (int nf = 0; nf < 8; nf++) {
            int col = warpn * 64 + nf * 8 + (lane & 3) * 2;
            if (r0 < nn)
                *(float2*)(g_xp + (size_t)r0 * DOUT + col) =
                    make_float2(d[mf][nf][0], d[mf][nf][1]);
            if (r0 + 8 < nn)
                *(float2*)(g_xp + (size_t)(r0 + 8) * DOUT + col) =
                    make_float2(d[mf][nf][2], d[mf][nf][3]);
        }
    }
}

// ---------------- CSR build --------------------------------------------------
__global__ void k_hist(const int* __restrict__ rows, int ne) {
    int i = blockIdx.x * blockDim.x + threadIdx.x;
    int b = i * 4;
    if (b + 3 < ne) {
        int4 r = *(const int4*)(rows + b);
        atomicAdd(&g_deg[r.x], 1);
        atomicAdd(&g_deg[r.y], 1);
        atomicAdd(&g_deg[r.z], 1);
        atomicAdd(&g_deg[r.w], 1);
    } else {
        for (int e = b; e < ne; e++) atomicAdd(&g_deg[rows[e]], 1);
    }
}

// single-block exclusive scan of g_deg -> g_rowptr
__global__ void __launch_bounds__(1024) k_scan(int n) {
    __shared__ int part[1024];
    int t = threadIdx.x;
    int per = (n + 1023) / 1024;
    int start = t * per;
    int end = min(start + per, n);
    int sum = 0;
    for (int i = start; i < end; i++) sum += g_deg[i];
    part[t] = sum;
    __syncthreads();
    for (int ofs = 1; ofs < 1024; ofs <<= 1) {
        int v = (t >= ofs) ? part[t - ofs] : 0;
        __syncthreads();
        part[t] += v;
        __syncthreads();
    }
    int run = (t == 0) ? 0 : part[t - 1];
    for (int i = start; i < end; i++) {
        int dg = g_deg[i];
        g_rowptr[i] = run;
        run += dg;
    }
    if (end == n && start <= n) g_rowptr[n] = run;
}

__global__ void k_scatter(const int* __restrict__ rows, const int* __restrict__ cols,
                          const float* __restrict__ vals, int ne) {
    int i = blockIdx.x * blockDim.x + threadIdx.x;
    int b = i * 4;
    if (b + 3 < ne) {
        int4   r = *(const int4*)(rows + b);
        int4   c = *(const int4*)(cols + b);
        float4 v = *(const float4*)(vals + b);
        int p0 = g_rowptr[r.x] + atomicAdd(&g_cursor[r.x], 1);
        g_edge[p0] = make_int2(c.x, __float_as_int(v.x));
        int p1 = g_rowptr[r.y] + atomicAdd(&g_cursor[r.y], 1);
        g_edge[p1] = make_int2(c.y, __float_as_int(v.y));
        int p2 = g_rowptr[r.z] + atomicAdd(&g_cursor[r.z], 1);
        g_edge[p2] = make_int2(c.z, __float_as_int(v.z));
        int p3 = g_rowptr[r.w] + atomicAdd(&g_cursor[r.w], 1);
        g_edge[p3] = make_int2(c.w, __float_as_int(v.w));
    } else {
        for (int e = b; e < ne; e++) {
            int dst = rows[e];
            int pos = g_rowptr[dst] + atomicAdd(&g_cursor[dst], 1);
            g_edge[pos] = make_int2(cols[e], __float_as_int(vals[e]));
        }
    }
}

// ---------------- SpMM + tanh: warp per destination row ---------------------
__global__ void __launch_bounds__(256) k_spmm(float* __restrict__ out, int n) {
    int warp = (blockIdx.x * blockDim.x + threadIdx.x) >> 5;
    int lane = threadIdx.x & 31;
    if (warp >= n) return;
    int beg = g_rowptr[warp];
    int end = g_rowptr[warp + 1];
    const float* xpb = g_xp + lane * 4;
    float4 acc = make_float4(0.f, 0.f, 0.f, 0.f);
    for (int b = beg; b < end; b += 32) {
        int idx = b + lane;
        int cc = 0; float vv = 0.f;
        if (idx < end) {
            int2 e = __ldg(&g_edge[idx]);
            cc = e.x; vv = __int_as_float(e.y);
        }
        int cnt = min(32, end - b);
        int cnt4 = (cnt + 3) & ~3;
        for (int j = 0; j < cnt4; j += 4) {
            int   c0 = __shfl_sync(0xffffffffu, cc, j);
            int   c1 = __shfl_sync(0xffffffffu, cc, j + 1);
            int   c2 = __shfl_sync(0xffffffffu, cc, j + 2);
            int   c3 = __shfl_sync(0xffffffffu, cc, j + 3);
            float v0 = __shfl_sync(0xffffffffu, vv, j);
            float v1 = __shfl_sync(0xffffffffu, vv, j + 1);
            float v2 = __shfl_sync(0xffffffffu, vv, j + 2);
            float v3 = __shfl_sync(0xffffffffu, vv, j + 3);
            float4 x0 = __ldg((const float4*)(xpb + (size_t)c0 * DOUT));
            float4 x1 = __ldg((const float4*)(xpb + (size_t)c1 * DOUT));
            float4 x2 = __ldg((const float4*)(xpb + (size_t)c2 * DOUT));
            float4 x3 = __ldg((const float4*)(xpb + (size_t)c3 * DOUT));
            acc.x = fmaf(v0, x0.x, acc.x); acc.y = fmaf(v0, x0.y, acc.y);
            acc.z = fmaf(v0, x0.z, acc.z); acc.w = fmaf(v0, x0.w, acc.w);
            acc.x = fmaf(v1, x1.x, acc.x); acc.y = fmaf(v1, x1.y, acc.y);
            acc.z = fmaf(v1, x1.z, acc.z); acc.w = fmaf(v1, x1.w, acc.w);
            acc.x = fmaf(v2, x2.x, acc.x); acc.y = fmaf(v2, x2.y, acc.y);
            acc.z = fmaf(v2, x2.z, acc.z); acc.w = fmaf(v2, x2.w, acc.w);
            acc.x = fmaf(v3, x3.x, acc.x); acc.y = fmaf(v3, x3.y, acc.y);
            acc.z = fmaf(v3, x3.z, acc.z); acc.w = fmaf(v3, x3.w, acc.w);
        }
    }
    float4 o;
    o.x = tanhf(acc.x); o.y = tanhf(acc.y);
    o.z = tanhf(acc.z); o.w = tanhf(acc.w);
    *(float4*)(out + (size_t)warp * DOUT + lane * 4) = o;
}

// ---------------- launch -----------------------------------------------------
extern "C" void kernel_launch(void* const* d_in, const int* in_sizes, int n_in,
                              void* d_out, int out_size) {
    const float* X    = (const float*)d_in[0];   // [N, 512]
    const float* W    = (const float*)d_in[1];   // [512, 128]
    const float* vals = (const float*)d_in[2];   // [E]
    const int*   rows = (const int*)d_in[3];     // [E]
    const int*   cols = (const int*)d_in[4];     // [E]
    float* out = (float*)d_out;

    int nn = in_sizes[0] / DIN;
    int ne = in_sizes[2];

    cudaFuncSetAttribute(k_chol,  cudaFuncAttributeMaxDynamicSharedMemorySize, 65536);
    cudaFuncSetAttribute(k_ortho, cudaFuncAttributeMaxDynamicSharedMemorySize, 131072);
    cudaFuncSetAttribute(k_gemm,  cudaFuncAttributeMaxDynamicSharedMemorySize, GEMM_SMEM);

    int zblocks = (2 * nn + 127) / 128;
    int e4 = (ne + 3) / 4;

    // launch order chosen so index 5 (ncu -s 5 -c 1) = k_gemm
    kA<<<DOUT + zblocks, 128>>>(W, nn);                          // 0: gram + zero
    k_hist<<<(e4 + 255) / 256, 256>>>(rows, ne);                 // 1
    k_chol<<<1, DOUT, 65536>>>();                                // 2
    k_scan<<<1, 1024>>>(nn);                                     // 3
    k_ortho<<<DIN / 128, 128, 131072>>>(W);                      // 4
    k_gemm<<<(nn + 127) / 128, 256, GEMM_SMEM>>>(X, nn);         // 5  <- profiled
    k_scatter<<<(e4 + 255) / 256, 256>>>(rows, cols, vals, ne);  // 6
    k_spmm<<<(nn * 32 + 255) / 256, 256>>>(out, nn);             // 7
}

// round 7
// speedup vs baseline: 1.7352x; 1.5891x over previous
#include <cuda_runtime.h>
#include <cuda_bf16.h>
#include <cstdint>
#include <cstring>
#include <math.h>

#define DIN  512
#define DOUT 128
#define MAXN 100000
#define MAXE 3200000

// ---------------- device-global scratch (no runtime allocation) ------------
__device__ __align__(16) float g_xp[(size_t)MAXN * DOUT];      // projected X
__device__ __align__(16) float g_G[DOUT * DOUT];               // gram -> chol L
__device__ __align__(16) __nv_bfloat16 g_wth[DOUT * DIN];      // W_ortho^T hi  [n][k]
__device__ __align__(16) __nv_bfloat16 g_wtl[DOUT * DIN];      // W_ortho^T lo  [n][k]
__device__ int   g_deg[MAXN];
__device__ int   g_rowptr[MAXN];
__device__ int   g_cursor[MAXN];
__device__ int   g_total;
__device__ __align__(8) int2 g_edge[MAXE];                     // .x=col .y=val bits

__device__ __forceinline__ uint32_t pack_bf16(__nv_bfloat16 a, __nv_bfloat16 b) {
    __nv_bfloat162 t(a, b);
    uint32_t r; memcpy(&r, &t, 4); return r;
}

__device__ __forceinline__ uint32_t smem_u32(const void* p) {
    return (uint32_t)__cvta_generic_to_shared(p);
}

// async 16B copy, L1-bypass
__device__ __forceinline__ void cp16(uint32_t s, const void* g) {
    asm volatile("cp.async.cg.shared.global [%0], [%1], 16;" :: "r"(s), "l"(g));
}
#define CP_COMMIT() asm volatile("cp.async.commit_group;")
#define CP_WAIT0()  asm volatile("cp.async.wait_group 0;")

// warp-level bf16 MMA (sm_80+; compiles on plain sm_100 target)
__device__ __forceinline__ void mma16816(float* d, const uint32_t* a, const uint32_t* b) {
    asm volatile("mma.sync.aligned.m16n8k16.row.col.f32.bf16.bf16.f32 "
        "{%0,%1,%2,%3}, {%4,%5,%6,%7}, {%8,%9}, {%0,%1,%2,%3};"
        : "+f"(d[0]), "+f"(d[1]), "+f"(d[2]), "+f"(d[3])
        : "r"(a[0]), "r"(a[1]), "r"(a[2]), "r"(a[3]), "r"(b[0]), "r"(b[1]));
}

// ---------------- kA: Gram matrix + zero deg/cursor/total --------------------
// blocks [0, 128): G = W^T W + 1e-4 I (block i = row i of G)
// blocks [128, ..): zero g_deg (first n idx) and g_cursor (next n idx)
__global__ void __launch_bounds__(128) kA(const float* __restrict__ W, int n) {
    if (blockIdx.x < DOUT) {
        __shared__ float col[DIN];
        int i = blockIdx.x, j = threadIdx.x;
        for (int k = j; k < DIN; k += DOUT) col[k] = W[k * DOUT + i];
        __syncthreads();
        float acc = 0.f;
        #pragma unroll 8
        for (int k = 0; k < DIN; k++) acc = fmaf(col[k], W[k * DOUT + j], acc);
        g_G[i * DOUT + j] = acc + (i == j ? 1e-4f : 0.f);
    } else {
        if (blockIdx.x == DOUT && threadIdx.x == 0) g_total = 0;
        int i = (blockIdx.x - DOUT) * 128 + threadIdx.x;
        if (i < n) g_deg[i] = 0;
        else if (i < 2 * n) g_cursor[i - n] = 0;
    }
}

// ---------------- Cholesky: 512 threads, 4 per row, pitch-129 smem ----------
// diag kept in side array so the sqrt read never races the normalize write.
static constexpr int CP_ = 129;
static constexpr int CHOL_SMEM = (DOUT * CP_ + DOUT) * 4;   // 66560 B

__global__ void __launch_bounds__(512) k_chol() {
    extern __shared__ float s[];
    float* diag = s + DOUT * CP_;
    int tid = threadIdx.x;
    int t = tid >> 2;        // row 0..127
    int q = tid & 3;         // column-quarter within row
    for (int idx = tid; idx < DOUT * DOUT; idx += 512) {
        int r = idx >> 7, c = idx & 127;
        s[r * CP_ + c] = g_G[idx];
    }
    __syncthreads();
    for (int k = 0; k < DOUT; k++) {
        float dk = sqrtf(s[k * CP_ + k]);    // s[k][k] is final; never rewritten
        if (tid == 0) diag[k] = dk;
        if (q == 0 && t > k) s[t * CP_ + k] /= dk;
        __syncthreads();
        if (t > k) {
            float lik = s[t * CP_ + k];
            for (int j = k + 1 + q; j <= t; j += 4)
                s[t * CP_ + j] -= lik * s[j * CP_ + k];
        }
        __syncthreads();
    }
    for (int idx = tid; idx < DOUT * DOUT; idx += 512) {
        int r = idx >> 7, c = idx & 127;
        g_G[idx] = (r == c) ? diag[r] : s[r * CP_ + c];
    }
}

// W_ortho row r solves L y = W[r,:]^T; store y^T bf16 hi/lo at [n=j][k=r].
__global__ void __launch_bounds__(128) k_ortho(const float* __restrict__ W) {
    extern __shared__ char s_raw[];
    float* Ls = (float*)s_raw;                // 128*128 floats
    float* ys = Ls + DOUT * DOUT;             // [j][thread]
    int t = threadIdx.x;
    for (int idx = t; idx < DOUT * DOUT; idx += 128) Ls[idx] = g_G[idx];
    __syncthreads();
    int r = blockIdx.x * 128 + t;             // 0..511 (k index)
    const float* wr = W + (size_t)r * DOUT;
    for (int j = 0; j < DOUT; j++) {
        float s0 = 0.f, s1 = 0.f, s2 = 0.f, s3 = 0.f;
        const float* lj = Ls + j * DOUT;
        int k = 0;
        for (; k + 3 < j; k += 4) {
            s0 = fmaf(lj[k],     ys[k * 128 + t],       s0);
            s1 = fmaf(lj[k + 1], ys[(k + 1) * 128 + t], s1);
            s2 = fmaf(lj[k + 2], ys[(k + 2) * 128 + t], s2);
            s3 = fmaf(lj[k + 3], ys[(k + 3) * 128 + t], s3);
        }
        for (; k < j; k++) s0 = fmaf(lj[k], ys[k * 128 + t], s0);
        float sv = (wr[j] - ((s0 + s1) + (s2 + s3))) / lj[j];
        ys[j * 128 + t] = sv;
        __nv_bfloat16 h = __float2bfloat16_rn(sv);
        float rem = sv - __bfloat162float(h);
        g_wth[j * DIN + r] = h;
        g_wtl[j * DIN + r] = __float2bfloat16_rn(rem);
    }
}

// ---------------- GEMM: Xp = X @ W_ortho  (mma.sync bf16 hi/lo split) -------
// CTA: 256 thr (8 warps), M=128, N=128, K chunks of 32, double-buffered smem.
// smem rows are 80 B (64 B data + 16 B pad) to avoid bank conflicts.
static constexpr int ST_ROW  = 80;
static constexpr int TILE_B  = 128 * ST_ROW;        // 10240
static constexpr int STAGE_B = 4 * TILE_B;          // 40960 (Ah, Al, Bh, Bl)
static constexpr int GEMM_SMEM = 2 * STAGE_B;       // 81920

__global__ void __launch_bounds__(256)
k_gemm(const float* __restrict__ X, int nn) {
    extern __shared__ char smem[];
    uint32_t sm0 = smem_u32(smem);
    int tid  = threadIdx.x;
    int lane = tid & 31;
    int wid  = tid >> 5;
    int warpm = wid & 3;          // 4 tiles of 32 rows
    int warpn = wid >> 2;         // 2 tiles of 64 cols
    int qrow = lane >> 2;         // 0..7
    int qk   = (lane & 3) * 4;    // byte offset within k16
    int m0 = blockIdx.x * 128;

    float d[2][8][4];
    #pragma unroll
    for (int mf = 0; mf < 2; mf++)
        #pragma unroll
        for (int nf = 0; nf < 8; nf++)
            #pragma unroll
            for (int q = 0; q < 4; q++) d[mf][nf][q] = 0.f;

    // A staging slots: idx = tid + t*256; row = idx>>3, kq = (idx&7)*4
    int srow[4], skq[4];
    #pragma unroll
    for (int t = 0; t < 4; t++) {
        int idx = tid + t * 256;
        srow[t] = idx >> 3;
        skq[t]  = (idx & 7) << 2;
    }
    // B cp.async slots: idx = tid + t*256; row = idx>>2, q = idx&3 (16B units)
    int brow[2], bq[2];
    #pragma unroll
    for (int t = 0; t < 2; t++) {
        int idx = tid + t * 256;
        brow[t] = idx >> 2;
        bq[t]   = (idx & 3) * 16;
    }

    // ---- prologue: chunk 0 ----
    {
        uint32_t sBh = sm0 + 2 * TILE_B, sBl = sm0 + 3 * TILE_B;
        #pragma unroll
        for (int t = 0; t < 2; t++) {
            int off = brow[t] * ST_ROW + bq[t];
            cp16(sBh + off, (const char*)(g_wth + (size_t)brow[t] * DIN) + bq[t]);
            cp16(sBl + off, (const char*)(g_wtl + (size_t)brow[t] * DIN) + bq[t]);
        }
        CP_COMMIT();
        char* st = smem;
        #pragma unroll
        for (int t = 0; t < 4; t++) {
            int row = srow[t], kq = skq[t];
            int m = m0 + row;
            float4 xv = make_float4(0.f, 0.f, 0.f, 0.f);
            if (m < nn) xv = *(const float4*)(X + (size_t)m * DIN + kq);
            __nv_bfloat16 h0 = __float2bfloat16_rn(xv.x), h1 = __float2bfloat16_rn(xv.y);
            __nv_bfloat16 h2 = __float2bfloat16_rn(xv.z), h3 = __float2bfloat16_rn(xv.w);
            uint2 hv; hv.x = pack_bf16(h0, h1); hv.y = pack_bf16(h2, h3);
            uint2 lv;
            lv.x = pack_bf16(__float2bfloat16_rn(xv.x - __bfloat162float(h0)),
                             __float2bfloat16_rn(xv.y - __bfloat162float(h1)));
            lv.y = pack_bf16(__float2bfloat16_rn(xv.z - __bfloat162float(h2)),
                             __float2bfloat16_rn(xv.w - __bfloat162float(h3)));
            int off = row * ST_ROW + kq * 2;
            *(uint2*)(st + off)          = hv;
            *(uint2*)(st + TILE_B + off) = lv;
        }
        CP_WAIT0();
    }
    __syncthreads();

    #pragma unroll 1
    for (int c = 0; c < 16; c++) {
        int s = c & 1;
        float4 areg[4];
        if (c < 15) {
            int koff = (c + 1) * 32;
            // B for chunk c+1 via cp.async into stage s^1
            uint32_t nst = sm0 + (uint32_t)(s ^ 1) * STAGE_B;
            #pragma unroll
            for (int t = 0; t < 2; t++) {
                int off = brow[t] * ST_ROW + bq[t];
                const char* gh = (const char*)(g_wth + (size_t)brow[t] * DIN + koff) + bq[t];
                const char* gl = (const char*)(g_wtl + (size_t)brow[t] * DIN + koff) + bq[t];
                cp16(nst + 2 * TILE_B + off, gh);
                cp16(nst + 3 * TILE_B + off, gl);
            }
            CP_COMMIT();
            // A for chunk c+1 into registers
            #pragma unroll
            for (int t = 0; t < 4; t++) {
                int m = m0 + srow[t];
                areg[t] = make_float4(0.f, 0.f, 0.f, 0.f);
                if (m < nn) areg[t] = *(const float4*)(X + (size_t)m * DIN + koff + skq[t]);
            }
        }

        // ---- compute on stage s ----
        const char* Ah = smem + s * STAGE_B;
        const char* Al = Ah + TILE_B;
        const char* Bh = Ah + 2 * TILE_B;
        const char* Bl = Ah + 3 * TILE_B;
        #pragma unroll
        for (int ks = 0; ks < 2; ks++) {
            uint32_t ahf[2][4], alf[2][4];
            #pragma unroll
            for (int mf = 0; mf < 2; mf++) {
                int byt = (warpm * 32 + mf * 16 + qrow) * ST_ROW + ks * 32 + qk;
                ahf[mf][0] = *(const uint32_t*)(Ah + byt);
                ahf[mf][1] = *(const uint32_t*)(Ah + byt + 8 * ST_ROW);
                ahf[mf][2] = *(const uint32_t*)(Ah + byt + 16);
                ahf[mf][3] = *(const uint32_t*)(Ah + byt + 8 * ST_ROW + 16);
                alf[mf][0] = *(const uint32_t*)(Al + byt);
                alf[mf][1] = *(const uint32_t*)(Al + byt + 8 * ST_ROW);
                alf[mf][2] = *(const uint32_t*)(Al + byt + 16);
                alf[mf][3] = *(const uint32_t*)(Al + byt + 8 * ST_ROW + 16);
            }
            #pragma unroll
            for (int nf = 0; nf < 8; nf++) {
                int byt = (warpn * 64 + nf * 8 + qrow) * ST_ROW + ks * 32 + qk;
                uint32_t bhf[2], blf[2];
                bhf[0] = *(const uint32_t*)(Bh + byt);
                bhf[1] = *(const uint32_t*)(Bh + byt + 16);
                blf[0] = *(const uint32_t*)(Bl + byt);
                blf[1] = *(const uint32_t*)(Bl + byt + 16);
                #pragma unroll
                for (int mf = 0; mf < 2; mf++) {
                    mma16816(d[mf][nf], ahf[mf], bhf);
                    mma16816(d[mf][nf], ahf[mf], blf);
                    mma16816(d[mf][nf], alf[mf], bhf);
                }
            }
        }

        if (c < 15) {
            // store staged A chunk c+1 into stage s^1
            char* st = smem + (s ^ 1) * STAGE_B;
            #pragma unroll
            for (int t = 0; t < 4; t++) {
                int row = srow[t], kq = skq[t];
                float4 xv = areg[t];
                __nv_bfloat16 h0 = __float2bfloat16_rn(xv.x), h1 = __float2bfloat16_rn(xv.y);
                __nv_bfloat16 h2 = __float2bfloat16_rn(xv.z), h3 = __float2bfloat16_rn(xv.w);
                uint2 hv; hv.x = pack_bf16(h0, h1); hv.y = pack_bf16(h2, h3);
                uint2 lv;
                lv.x = pack_bf16(__float2bfloat16_rn(xv.x - __bfloat162float(h0)),
                                 __float2bfloat16_rn(xv.y - __bfloat162float(h1)));
                lv.y = pack_bf16(__float2bfloat16_rn(xv.z - __bfloat162float(h2)),
                                 __float2bfloat16_rn(xv.w - __bfloat162float(h3)));
                int off = row * ST_ROW + kq * 2;
                *(uint2*)(st + off)          = hv;
                *(uint2*)(st + TILE_B + off) = lv;
            }
        }
        CP_WAIT0();
        __syncthreads();
    }

    // ---- epilogue: write Xp ----
    #pragma unroll
    for (int mf = 0; mf < 2; mf++) {
        int r0 = m0 + warpm * 32 + mf * 16 + qrow;
        #pragma unroll
        for (int nf = 0; nf < 8; nf++) {
            int col = warpn * 64 + nf * 8 + (lane & 3) * 2;
            if (r0 < nn)
                *(float2*)(g_xp + (size_t)r0 * DOUT + col) =
                    make_float2(d[mf][nf][0], d[mf][nf][1]);
            if (r0 + 8 < nn)
                *(float2*)(g_xp + (size_t)(r0 + 8) * DOUT + col) =
                    make_float2(d[mf][nf][2], d[mf][nf][3]);
        }
    }
}

// ---------------- CSR build --------------------------------------------------
__global__ void k_hist(const int* __restrict__ rows, int ne) {
    int i = blockIdx.x * blockDim.x + threadIdx.x;
    int b = i * 4;
    if (b + 3 < ne) {
        int4 r = *(const int4*)(rows + b);
        atomicAdd(&g_deg[r.x], 1);
        atomicAdd(&g_deg[r.y], 1);
        atomicAdd(&g_deg[r.z], 1);
        atomicAdd(&g_deg[r.w], 1);
    } else {
        for (int e = b; e < ne; e++) atomicAdd(&g_deg[rows[e]], 1);
    }
}

// row-base allocation: warp-aggregated atomic (replaces 100us 1-block scan)
__global__ void k_alloc(int n) {
    int i = blockIdx.x * blockDim.x + threadIdx.x;
    int lane = threadIdx.x & 31;
    int d = (i < n) ? g_deg[i] : 0;
    int incl = d;
    #pragma unroll
    for (int o = 1; o < 32; o <<= 1) {
        int v = __shfl_up_sync(0xffffffffu, incl, o);
        if (lane >= o) incl += v;
    }
    int wsum = __shfl_sync(0xffffffffu, incl, 31);
    int base = 0;
    if (lane == 31 && wsum > 0) base = atomicAdd(&g_total, wsum);
    base = __shfl_sync(0xffffffffu, base, 31);
    if (i < n) g_rowptr[i] = base + incl - d;
}

__global__ void k_scatter(const int* __restrict__ rows, const int* __restrict__ cols,
                          const float* __restrict__ vals, int ne) {
    int i = blockIdx.x * blockDim.x + threadIdx.x;
    int b = i * 4;
    if (b + 3 < ne) {
        int4   r = *(const int4*)(rows + b);
        int4   c = *(const int4*)(cols + b);
        float4 v = *(const float4*)(vals + b);
        int p0 = g_rowptr[r.x] + atomicAdd(&g_cursor[r.x], 1);
        g_edge[p0] = make_int2(c.x, __float_as_int(v.x));
        int p1 = g_rowptr[r.y] + atomicAdd(&g_cursor[r.y], 1);
        g_edge[p1] = make_int2(c.y, __float_as_int(v.y));
        int p2 = g_rowptr[r.z] + atomicAdd(&g_cursor[r.z], 1);
        g_edge[p2] = make_int2(c.z, __float_as_int(v.z));
        int p3 = g_rowptr[r.w] + atomicAdd(&g_cursor[r.w], 1);
        g_edge[p3] = make_int2(c.w, __float_as_int(v.w));
    } else {
        for (int e = b; e < ne; e++) {
            int dst = rows[e];
            int pos = g_rowptr[dst] + atomicAdd(&g_cursor[dst], 1);
            g_edge[pos] = make_int2(cols[e], __float_as_int(vals[e]));
        }
    }
}

// ---------------- SpMM + tanh: warp per destination row ---------------------
__global__ void __launch_bounds__(256) k_spmm(float* __restrict__ out, int n) {
    int warp = (blockIdx.x * blockDim.x + threadIdx.x) >> 5;
    int lane = threadIdx.x & 31;
    if (warp >= n) return;
    int beg = g_rowptr[warp];
    int end = beg + g_deg[warp];
    const float* xpb = g_xp + lane * 4;
    float4 acc = make_float4(0.f, 0.f, 0.f, 0.f);
    for (int b = beg; b < end; b += 32) {
        int idx = b + lane;
        int cc = 0; float vv = 0.f;
        if (idx < end) {
            int2 e = __ldg(&g_edge[idx]);
            cc = e.x; vv = __int_as_float(e.y);
        }
        int cnt = min(32, end - b);
        int cnt4 = (cnt + 3) & ~3;
        for (int j = 0; j < cnt4; j += 4) {
            int   c0 = __shfl_sync(0xffffffffu, cc, j);
            int   c1 = __shfl_sync(0xffffffffu, cc, j + 1);
            int   c2 = __shfl_sync(0xffffffffu, cc, j + 2);
            int   c3 = __shfl_sync(0xffffffffu, cc, j + 3);
            float v0 = __shfl_sync(0xffffffffu, vv, j);
            float v1 = __shfl_sync(0xffffffffu, vv, j + 1);
            float v2 = __shfl_sync(0xffffffffu, vv, j + 2);
            float v3 = __shfl_sync(0xffffffffu, vv, j + 3);
            float4 x0 = __ldg((const float4*)(xpb + (size_t)c0 * DOUT));
            float4 x1 = __ldg((const float4*)(xpb + (size_t)c1 * DOUT));
            float4 x2 = __ldg((const float4*)(xpb + (size_t)c2 * DOUT));
            float4 x3 = __ldg((const float4*)(xpb + (size_t)c3 * DOUT));
            acc.x = fmaf(v0, x0.x, acc.x); acc.y = fmaf(v0, x0.y, acc.y);
            acc.z = fmaf(v0, x0.z, acc.z); acc.w = fmaf(v0, x0.w, acc.w);
            acc.x = fmaf(v1, x1.x, acc.x); acc.y = fmaf(v1, x1.y, acc.y);
            acc.z = fmaf(v1, x1.z, acc.z); acc.w = fmaf(v1, x1.w, acc.w);
            acc.x = fmaf(v2, x2.x, acc.x); acc.y = fmaf(v2, x2.y, acc.y);
            acc.z = fmaf(v2, x2.z, acc.z); acc.w = fmaf(v2, x2.w, acc.w);
            acc.x = fmaf(v3, x3.x, acc.x); acc.y = fmaf(v3, x3.y, acc.y);
            acc.z = fmaf(v3, x3.z, acc.z); acc.w = fmaf(v3, x3.w, acc.w);
        }
    }
    float4 o;
    o.x = tanhf(acc.x); o.y = tanhf(acc.y);
    o.z = tanhf(acc.z); o.w = tanhf(acc.w);
    *(float4*)(out + (size_t)warp * DOUT + lane * 4) = o;
}

// ---------------- launch -----------------------------------------------------
extern "C" void kernel_launch(void* const* d_in, const int* in_sizes, int n_in,
                              void* d_out, int out_size) {
    const float* X    = (const float*)d_in[0];   // [N, 512]
    const float* W    = (const float*)d_in[1];   // [512, 128]
    const float* vals = (const float*)d_in[2];   // [E]
    const int*   rows = (const int*)d_in[3];     // [E]
    const int*   cols = (const int*)d_in[4];     // [E]
    float* out = (float*)d_out;

    int nn = in_sizes[0] / DIN;
    int ne = in_sizes[2];

    cudaFuncSetAttribute(k_chol,  cudaFuncAttributeMaxDynamicSharedMemorySize, CHOL_SMEM);
    cudaFuncSetAttribute(k_ortho, cudaFuncAttributeMaxDynamicSharedMemorySize, 131072);
    cudaFuncSetAttribute(k_gemm,  cudaFuncAttributeMaxDynamicSharedMemorySize, GEMM_SMEM);

    int zblocks = (2 * nn + 127) / 128;
    int e4 = (ne + 3) / 4;

    // ncu lands on launch index 3 -> place k_gemm there
    kA<<<DOUT + zblocks, 128>>>(W, nn);                          // 0: gram + zeroing
    k_chol<<<1, 512, CHOL_SMEM>>>();                             // 1
    k_ortho<<<DIN / 128, 128, 131072>>>(W);                      // 2
    k_gemm<<<(nn + 127) / 128, 256, GEMM_SMEM>>>(X, nn);         // 3  <- profiled
    k_hist<<<(e4 + 255) / 256, 256>>>(rows, ne);                 // 4
    k_alloc<<<(nn + 255) / 256, 256>>>(nn);                      // 5
    k_scatter<<<(e4 + 255) / 256, 256>>>(rows, cols, vals, ne);  // 6
    k_spmm<<<(nn * 32 + 255) / 256, 256>>>(out, nn);             // 7
}

// round 10
// speedup vs baseline: 1.8448x; 1.0632x over previous
#include <cuda_runtime.h>
#include <cuda_bf16.h>
#include <cstdint>
#include <cstring>
#include <math.h>

#define DIN  512
#define DOUT 128
#define MAXN 100000
#define MAXE 3200000

// ---------------- device-global scratch (no runtime allocation) ------------
__device__ __align__(16) float g_xp[(size_t)MAXN * DOUT];      // projected X
__device__ __align__(16) float g_G[DOUT * DOUT];               // gram -> chol L
__device__ __align__(16) __nv_bfloat16 g_wth[DOUT * DIN];      // W_ortho^T hi  [n][k]
__device__ __align__(16) __nv_bfloat16 g_wtl[DOUT * DIN];      // W_ortho^T lo  [n][k]
__device__ int   g_deg[MAXN];
__device__ int   g_rowptr[MAXN];
__device__ int   g_cursor[MAXN];
__device__ int   g_total;
__device__ __align__(8) int2 g_edge[MAXE];                     // .x=col .y=val bits

__device__ __forceinline__ uint32_t pack_bf16(__nv_bfloat16 a, __nv_bfloat16 b) {
    __nv_bfloat162 t(a, b);
    uint32_t r; memcpy(&r, &t, 4); return r;
}

__device__ __forceinline__ uint32_t smem_u32(const void* p) {
    return (uint32_t)__cvta_generic_to_shared(p);
}

// async 16B copy, L1-bypass
__device__ __forceinline__ void cp16(uint32_t s, const void* g) {
    asm volatile("cp.async.cg.shared.global [%0], [%1], 16;" :: "r"(s), "l"(g));
}
#define CP_COMMIT() asm volatile("cp.async.commit_group;")
#define CP_WAIT0()  asm volatile("cp.async.wait_group 0;")

// warp-level bf16 MMA (sm_80+; compiles on plain sm_100 target)
__device__ __forceinline__ void mma16816(float* d, const uint32_t* a, const uint32_t* b) {
    asm volatile("mma.sync.aligned.m16n8k16.row.col.f32.bf16.bf16.f32 "
        "{%0,%1,%2,%3}, {%4,%5,%6,%7}, {%8,%9}, {%0,%1,%2,%3};"
        : "+f"(d[0]), "+f"(d[1]), "+f"(d[2]), "+f"(d[3])
        : "r"(a[0]), "r"(a[1]), "r"(a[2]), "r"(a[3]), "r"(b[0]), "r"(b[1]));
}

__device__ __forceinline__ void ldm_x4(uint32_t* r, uint32_t addr) {
    asm volatile("ldmatrix.sync.aligned.m8n8.x4.shared.b16 {%0,%1,%2,%3}, [%4];"
        : "=r"(r[0]), "=r"(r[1]), "=r"(r[2]), "=r"(r[3]) : "r"(addr));
}

// XOR swizzle on 64B rows packed in 128B lines: bits[4:6] ^= bits[7:9]
__device__ __forceinline__ uint32_t swz(uint32_t off) {
    return off ^ ((off >> 3) & 0x70);
}

// ---------------- kA: Gram matrix + zero deg/cursor/total --------------------
__global__ void __launch_bounds__(128) kA(const float* __restrict__ W, int n) {
    if (blockIdx.x < DOUT) {
        __shared__ float col[DIN];
        int i = blockIdx.x, j = threadIdx.x;
        for (int k = j; k < DIN; k += DOUT) col[k] = W[k * DOUT + i];
        __syncthreads();
        float acc = 0.f;
        #pragma unroll 8
        for (int k = 0; k < DIN; k++) acc = fmaf(col[k], W[k * DOUT + j], acc);
        g_G[i * DOUT + j] = acc + (i == j ? 1e-4f : 0.f);
    } else {
        if (blockIdx.x == DOUT && threadIdx.x == 0) g_total = 0;
        int i = (blockIdx.x - DOUT) * 128 + threadIdx.x;
        if (i < n) g_deg[i] = 0;
        else if (i < 2 * n) g_cursor[i - n] = 0;
    }
}

// ---------------- Cholesky: 512 threads, 4 per row, pitch-129 smem ----------
static constexpr int CP_ = 129;
static constexpr int CHOL_SMEM = (DOUT * CP_ + DOUT) * 4;   // 66560 B

__global__ void __launch_bounds__(512) k_chol() {
    extern __shared__ float s[];
    float* diag = s + DOUT * CP_;
    int tid = threadIdx.x;
    int t = tid >> 2;        // row 0..127
    int q = tid & 3;         // column-quarter within row
    for (int idx = tid; idx < DOUT * DOUT; idx += 512) {
        int r = idx >> 7, c = idx & 127;
        s[r * CP_ + c] = g_G[idx];
    }
    __syncthreads();
    for (int k = 0; k < DOUT; k++) {
        float dk = sqrtf(s[k * CP_ + k]);
        if (tid == 0) diag[k] = dk;
        if (q == 0 && t > k) s[t * CP_ + k] /= dk;
        __syncthreads();
        if (t > k) {
            float lik = s[t * CP_ + k];
            for (int j = k + 1 + q; j <= t; j += 4)
                s[t * CP_ + j] -= lik * s[j * CP_ + k];
        }
        __syncthreads();
    }
    for (int idx = tid; idx < DOUT * DOUT; idx += 512) {
        int r = idx >> 7, c = idx & 127;
        g_G[idx] = (r == c) ? diag[r] : s[r * CP_ + c];
    }
}

// W_ortho row r solves L y = W[r,:]^T; store y^T bf16 hi/lo at [n=j][k=r].
__global__ void __launch_bounds__(128) k_ortho(const float* __restrict__ W) {
    extern __shared__ char s_raw[];
    float* Ls = (float*)s_raw;                // 128*128 floats
    float* ys = Ls + DOUT * DOUT;             // [j][thread]
    int t = threadIdx.x;
    for (int idx = t; idx < DOUT * DOUT; idx += 128) Ls[idx] = g_G[idx];
    __syncthreads();
    int r = blockIdx.x * 128 + t;             // 0..511 (k index)
    const float* wr = W + (size_t)r * DOUT;
    for (int j = 0; j < DOUT; j++) {
        float s0 = 0.f, s1 = 0.f, s2 = 0.f, s3 = 0.f;
        const float* lj = Ls + j * DOUT;
        int k = 0;
        for (; k + 3 < j; k += 4) {
            s0 = fmaf(lj[k],     ys[k * 128 + t],       s0);
            s1 = fmaf(lj[k + 1], ys[(k + 1) * 128 + t], s1);
            s2 = fmaf(lj[k + 2], ys[(k + 2) * 128 + t], s2);
            s3 = fmaf(lj[k + 3], ys[(k + 3) * 128 + t], s3);
        }
        for (; k < j; k++) s0 = fmaf(lj[k], ys[k * 128 + t], s0);
        float sv = (wr[j] - ((s0 + s1) + (s2 + s3))) / lj[j];
        ys[j * 128 + t] = sv;
        __nv_bfloat16 h = __float2bfloat16_rn(sv);
        float rem = sv - __bfloat162float(h);
        g_wth[j * DIN + r] = h;
        g_wtl[j * DIN + r] = __float2bfloat16_rn(rem);
    }
}

// ---------------- GEMM: Xp = X @ W_ortho  (mma.sync bf16 hi/lo split) -------
// CTA: 256 thr (8 warps), M=128, N=128, K chunks of 32, double-buffered,
// XOR-swizzled 64B rows (no padding), ldmatrix fragment loads, 2 CTAs/SM.
static constexpr int TILE_B  = 128 * 64;            // 8192
static constexpr int STAGE_B = 4 * TILE_B;          // 32768 (Ah, Al, Bh, Bl)
static constexpr int GEMM_SMEM = 2 * STAGE_B;       // 65536

__global__ void __launch_bounds__(256, 2)
k_gemm(const float* __restrict__ X, int nn) {
    extern __shared__ char smem[];
    uint32_t sm0 = smem_u32(smem);
    int tid  = threadIdx.x;
    int lane = tid & 31;
    int wid  = tid >> 5;
    int warpm = wid & 3;          // 4 tiles of 32 rows
    int warpn = wid >> 2;         // 2 tiles of 64 cols
    int m0 = blockIdx.x * 128;

    float d[2][8][4];
    #pragma unroll
    for (int mf = 0; mf < 2; mf++)
        #pragma unroll
        for (int nf = 0; nf < 8; nf++)
            #pragma unroll
            for (int q = 0; q < 4; q++) d[mf][nf][q] = 0.f;

    // A staging slots: idx = tid + t*256; row = idx>>3, 8B at (idx&7)*8
    int srow[4], skq[4];
    #pragma unroll
    for (int t = 0; t < 4; t++) {
        int idx = tid + t * 256;
        srow[t] = idx >> 3;
        skq[t]  = (idx & 7) << 2;   // float offset (0..28); byte off = *8 for bf16x4
    }
    // B cp.async slots: idx = tid + t*256; n = idx>>2, 16B at (idx&3)*16
    int brow[2], bq[2];
    #pragma unroll
    for (int t = 0; t < 2; t++) {
        int idx = tid + t * 256;
        brow[t] = idx >> 2;
        bq[t]   = (idx & 3) * 16;
    }

    // ldmatrix per-lane swizzled offsets (within a tile)
    // A x4: matrices (m0-7,k0-7),(m8-15,k0-7),(m0-7,k8-15),(m8-15,k8-15)
    uint32_t aoff[2][2];  // [mf][ks]
    {
        int arow = warpm * 32 + ((lane >> 3) & 1) * 8 + (lane & 7);
        int akb  = (lane >> 4) << 4;        // 0 or 16
        #pragma unroll
        for (int mf = 0; mf < 2; mf++)
            #pragma unroll
            for (int ks = 0; ks < 2; ks++)
                aoff[mf][ks] = swz((uint32_t)((arow + mf * 16) * 64 + ks * 32 + akb));
    }
    // B x4 for nf pair np: matrices (nf,k0-7),(nf,k8-15),(nf+1,k0-7),(nf+1,k8-15)
    uint32_t boff[4][2];  // [np][ks]
    {
        int bn  = warpn * 64 + ((lane >= 16) ? 8 : 0) + (lane & 7);
        int bkb = ((lane >> 3) & 1) * 16;
        #pragma unroll
        for (int np = 0; np < 4; np++)
            #pragma unroll
            for (int ks = 0; ks < 2; ks++)
                boff[np][ks] = swz((uint32_t)((bn + np * 16) * 64 + ks * 32 + bkb));
    }

    // ---- prologue: chunk 0 ----
    {
        uint32_t sBh = sm0 + 2 * TILE_B, sBl = sm0 + 3 * TILE_B;
        #pragma unroll
        for (int t = 0; t < 2; t++) {
            uint32_t off = swz((uint32_t)(brow[t] * 64 + bq[t]));
            cp16(sBh + off, (const char*)(g_wth + (size_t)brow[t] * DIN) + bq[t]);
            cp16(sBl + off, (const char*)(g_wtl + (size_t)brow[t] * DIN) + bq[t]);
        }
        CP_COMMIT();
        #pragma unroll
        for (int t = 0; t < 4; t++) {
            int row = srow[t], kq = skq[t];
            int m = m0 + row;
            float4 xv = make_float4(0.f, 0.f, 0.f, 0.f);
            if (m < nn) xv = *(const float4*)(X + (size_t)m * DIN + kq);
            __nv_bfloat16 h0 = __float2bfloat16_rn(xv.x), h1 = __float2bfloat16_rn(xv.y);
            __nv_bfloat16 h2 = __float2bfloat16_rn(xv.z), h3 = __float2bfloat16_rn(xv.w);
            uint2 hv; hv.x = pack_bf16(h0, h1); hv.y = pack_bf16(h2, h3);
            uint2 lv;
            lv.x = pack_bf16(__float2bfloat16_rn(xv.x - __bfloat162float(h0)),
                             __float2bfloat16_rn(xv.y - __bfloat162float(h1)));
            lv.y = pack_bf16(__float2bfloat16_rn(xv.z - __bfloat162float(h2)),
                             __float2bfloat16_rn(xv.w - __bfloat162float(h3)));
            uint32_t off = swz((uint32_t)(row * 64 + kq * 2));
            *(uint64_t*)(smem + off)          = *(uint64_t*)&hv;
            *(uint64_t*)(smem + TILE_B + off) = *(uint64_t*)&lv;
        }
        CP_WAIT0();
    }
    __syncthreads();

    #pragma unroll 1
    for (int c = 0; c < 16; c++) {
        int s = c & 1;
        float4 areg[4];
        if (c < 15) {
            int koff = (c + 1) * 32;
            uint32_t nst = sm0 + (uint32_t)(s ^ 1) * STAGE_B;
            #pragma unroll
            for (int t = 0; t < 2; t++) {
                uint32_t off = swz((uint32_t)(brow[t] * 64 + bq[t]));
                cp16(nst + 2 * TILE_B + off,
                     (const char*)(g_wth + (size_t)brow[t] * DIN + koff) + bq[t]);
                cp16(nst + 3 * TILE_B + off,
                     (const char*)(g_wtl + (size_t)brow[t] * DIN + koff) + bq[t]);
            }
            CP_COMMIT();
            #pragma unroll
            for (int t = 0; t < 4; t++) {
                int m = m0 + srow[t];
                areg[t] = make_float4(0.f, 0.f, 0.f, 0.f);
                if (m < nn) areg[t] = *(const float4*)(X + (size_t)m * DIN + koff + skq[t]);
            }
        }

        // ---- compute on stage s ----
        uint32_t stb = sm0 + (uint32_t)s * STAGE_B;
        #pragma unroll
        for (int ks = 0; ks < 2; ks++) {
            uint32_t ahf[2][4], alf[2][4];
            #pragma unroll
            for (int mf = 0; mf < 2; mf++) {
                ldm_x4(ahf[mf], stb + aoff[mf][ks]);
                ldm_x4(alf[mf], stb + TILE_B + aoff[mf][ks]);
            }
            #pragma unroll
            for (int np = 0; np < 4; np++) {
                uint32_t bh4[4], bl4[4];
                ldm_x4(bh4, stb + 2 * TILE_B + boff[np][ks]);
                ldm_x4(bl4, stb + 3 * TILE_B + boff[np][ks]);
                #pragma unroll
                for (int sub = 0; sub < 2; sub++) {
                    int nf = np * 2 + sub;
                    #pragma unroll
                    for (int mf = 0; mf < 2; mf++) {
                        mma16816(d[mf][nf], ahf[mf], bh4 + 2 * sub);
                        mma16816(d[mf][nf], ahf[mf], bl4 + 2 * sub);
                        mma16816(d[mf][nf], alf[mf], bh4 + 2 * sub);
                    }
                }
            }
        }

        if (c < 15) {
            char* st = smem + (size_t)(s ^ 1) * STAGE_B;
            #pragma unroll
            for (int t = 0; t < 4; t++) {
                int row = srow[t], kq = skq[t];
                float4 xv = areg[t];
                __nv_bfloat16 h0 = __float2bfloat16_rn(xv.x), h1 = __float2bfloat16_rn(xv.y);
                __nv_bfloat16 h2 = __float2bfloat16_rn(xv.z), h3 = __float2bfloat16_rn(xv.w);
                uint2 hv; hv.x = pack_bf16(h0, h1); hv.y = pack_bf16(h2, h3);
                uint2 lv;
                lv.x = pack_bf16(__float2bfloat16_rn(xv.x - __bfloat162float(h0)),
                                 __float2bfloat16_rn(xv.y - __bfloat162float(h1)));
                lv.y = pack_bf16(__float2bfloat16_rn(xv.z - __bfloat162float(h2)),
                                 __float2bfloat16_rn(xv.w - __bfloat162float(h3)));
                uint32_t off = swz((uint32_t)(row * 64 + kq * 2));
                *(uint64_t*)(st + off)          = *(uint64_t*)&hv;
                *(uint64_t*)(st + TILE_B + off) = *(uint64_t*)&lv;
            }
        }
        CP_WAIT0();
        __syncthreads();
    }

    // ---- epilogue: write Xp ----
    int qrow = lane >> 2;
    #pragma unroll
    for (int mf = 0; mf < 2; mf++) {
        int r0 = m0 + warpm * 32 + mf * 16 + qrow;
        #pragma unroll
        for (int nf = 0; nf < 8; nf++) {
            int col = warpn * 64 + nf * 8 + (lane & 3) * 2;
            if (r0 < nn)
                *(float2*)(g_xp + (size_t)r0 * DOUT + col) =
                    make_float2(d[mf][nf][0], d[mf][nf][1]);
            if (r0 + 8 < nn)
                *(float2*)(g_xp + (size_t)(r0 + 8) * DOUT + col) =
                    make_float2(d[mf][nf][2], d[mf][nf][3]);
        }
    }
}

// ---------------- CSR build --------------------------------------------------
__global__ void k_hist(const int* __restrict__ rows, int ne) {
    int i = blockIdx.x * blockDim.x + threadIdx.x;
    int b = i * 4;
    if (b + 3 < ne) {
        int4 r = *(const int4*)(rows + b);
        atomicAdd(&g_deg[r.x], 1);
        atomicAdd(&g_deg[r.y], 1);
        atomicAdd(&g_deg[r.z], 1);
        atomicAdd(&g_deg[r.w], 1);
    } else {
        for (int e = b; e < ne; e++) atomicAdd(&g_deg[rows[e]], 1);
    }
}

// row-base allocation: warp-aggregated atomic
__global__ void k_alloc(int n) {
    int i = blockIdx.x * blockDim.x + threadIdx.x;
    int lane = threadIdx.x & 31;
    int d = (i < n) ? g_deg[i] : 0;
    int incl = d;
    #pragma unroll
    for (int o = 1; o < 32; o <<= 1) {
        int v = __shfl_up_sync(0xffffffffu, incl, o);
        if (lane >= o) incl += v;
    }
    int wsum = __shfl_sync(0xffffffffu, incl, 31);
    int base = 0;
    if (lane == 31 && wsum > 0) base = atomicAdd(&g_total, wsum);
    base = __shfl_sync(0xffffffffu, base, 31);
    if (i < n) g_rowptr[i] = base + incl - d;
}

__global__ void k_scatter(const int* __restrict__ rows, const int* __restrict__ cols,
                          const float* __restrict__ vals, int ne) {
    int i = blockIdx.x * blockDim.x + threadIdx.x;
    int b = i * 4;
    if (b + 3 < ne) {
        int4   r = *(const int4*)(rows + b);
        int4   c = *(const int4*)(cols + b);
        float4 v = *(const float4*)(vals + b);
        int p0 = g_rowptr[r.x] + atomicAdd(&g_cursor[r.x], 1);
        g_edge[p0] = make_int2(c.x, __float_as_int(v.x));
        int p1 = g_rowptr[r.y] + atomicAdd(&g_cursor[r.y], 1);
        g_edge[p1] = make_int2(c.y, __float_as_int(v.y));
        int p2 = g_rowptr[r.z] + atomicAdd(&g_cursor[r.z], 1);
        g_edge[p2] = make_int2(c.z, __float_as_int(v.z));
        int p3 = g_rowptr[r.w] + atomicAdd(&g_cursor[r.w], 1);
        g_edge[p3] = make_int2(c.w, __float_as_int(v.w));
    } else {
        for (int e = b; e < ne; e++) {
            int dst = rows[e];
            int pos = g_rowptr[dst] + atomicAdd(&g_cursor[dst], 1);
            g_edge[pos] = make_int2(cols[e], __float_as_int(vals[e]));
        }
    }
}

// ---------------- SpMM + tanh: warp per destination row ---------------------
__global__ void __launch_bounds__(256) k_spmm(float* __restrict__ out, int n) {
    int warp = (blockIdx.x * blockDim.x + threadIdx.x) >> 5;
    int lane = threadIdx.x & 31;
    if (warp >= n) return;
    int beg = g_rowptr[warp];
    int end = beg + g_deg[warp];
    const float* xpb = g_xp + lane * 4;
    float4 acc = make_float4(0.f, 0.f, 0.f, 0.f);
    for (int b = beg; b < end; b += 32) {
        int idx = b + lane;
        int cc = 0; float vv = 0.f;
        if (idx < end) {
            int2 e = __ldg(&g_edge[idx]);
            cc = e.x; vv = __int_as_float(e.y);
        }
        int cnt = min(32, end - b);
        int cnt4 = (cnt + 3) & ~3;
        for (int j = 0; j < cnt4; j += 4) {
            int   c0 = __shfl_sync(0xffffffffu, cc, j);
            int   c1 = __shfl_sync(0xffffffffu, cc, j + 1);
            int   c2 = __shfl_sync(0xffffffffu, cc, j + 2);
            int   c3 = __shfl_sync(0xffffffffu, cc, j + 3);
            float v0 = __shfl_sync(0xffffffffu, vv, j);
            float v1 = __shfl_sync(0xffffffffu, vv, j + 1);
            float v2 = __shfl_sync(0xffffffffu, vv, j + 2);
            float v3 = __shfl_sync(0xffffffffu, vv, j + 3);
            float4 x0 = __ldg((const float4*)(xpb + (size_t)c0 * DOUT));
            float4 x1 = __ldg((const float4*)(xpb + (size_t)c1 * DOUT));
            float4 x2 = __ldg((const float4*)(xpb + (size_t)c2 * DOUT));
            float4 x3 = __ldg((const float4*)(xpb + (size_t)c3 * DOUT));
            acc.x = fmaf(v0, x0.x, acc.x); acc.y = fmaf(v0, x0.y, acc.y);
            acc.z = fmaf(v0, x0.z, acc.z); acc.w = fmaf(v0, x0.w, acc.w);
            acc.x = fmaf(v1, x1.x, acc.x); acc.y = fmaf(v1, x1.y, acc.y);
            acc.z = fmaf(v1, x1.z, acc.z); acc.w = fmaf(v1, x1.w, acc.w);
            acc.x = fmaf(v2, x2.x, acc.x); acc.y = fmaf(v2, x2.y, acc.y);
            acc.z = fmaf(v2, x2.z, acc.z); acc.w = fmaf(v2, x2.w, acc.w);
            acc.x = fmaf(v3, x3.x, acc.x); acc.y = fmaf(v3, x3.y, acc.y);
            acc.z = fmaf(v3, x3.z, acc.z); acc.w = fmaf(v3, x3.w, acc.w);
        }
    }
    float4 o;
    o.x = tanhf(acc.x); o.y = tanhf(acc.y);
    o.z = tanhf(acc.z); o.w = tanhf(acc.w);
    *(float4*)(out + (size_t)warp * DOUT + lane * 4) = o;
}

// ---------------- launch -----------------------------------------------------
extern "C" void kernel_launch(void* const* d_in, const int* in_sizes, int n_in,
                              void* d_out, int out_size) {
    const float* X    = (const float*)d_in[0];   // [N, 512]
    const float* W    = (const float*)d_in[1];   // [512, 128]
    const float* vals = (const float*)d_in[2];   // [E]
    const int*   rows = (const int*)d_in[3];     // [E]
    const int*   cols = (const int*)d_in[4];     // [E]
    float* out = (float*)d_out;

    int nn = in_sizes[0] / DIN;
    int ne = in_sizes[2];

    cudaFuncSetAttribute(k_chol,  cudaFuncAttributeMaxDynamicSharedMemorySize, CHOL_SMEM);
    cudaFuncSetAttribute(k_ortho, cudaFuncAttributeMaxDynamicSharedMemorySize, 131072);
    cudaFuncSetAttribute(k_gemm,  cudaFuncAttributeMaxDynamicSharedMemorySize, GEMM_SMEM);

    int zblocks = (2 * nn + 127) / 128;
    int e4 = (ne + 3) / 4;

    // ncu lands on launch index 3 -> keep k_gemm there to verify this round's fix
    kA<<<DOUT + zblocks, 128>>>(W, nn);                          // 0: gram + zeroing
    k_chol<<<1, 512, CHOL_SMEM>>>();                             // 1
    k_ortho<<<DIN / 128, 128, 131072>>>(W);                      // 2
    k_gemm<<<(nn + 127) / 128, 256, GEMM_SMEM>>>(X, nn);         // 3  <- profiled
    k_hist<<<(e4 + 255) / 256, 256>>>(rows, ne);                 // 4
    k_alloc<<<(nn + 255) / 256, 256>>>(nn);                      // 5
    k_scatter<<<(e4 + 255) / 256, 256>>>(rows, cols, vals, ne);  // 6
    k_spmm<<<(nn * 32 + 255) / 256, 256>>>(out, nn);             // 7
}

// round 11
// speedup vs baseline: 1.9853x; 1.0761x over previous
#include <cuda_runtime.h>
#include <cuda_bf16.h>
#include <cuda_fp16.h>
#include <cstdint>
#include <cstring>
#include <math.h>

#define DIN  512
#define DOUT 128
#define MAXN 100000
#define MAXE 3200000

// ---------------- device-global scratch (no runtime allocation) ------------
__device__ __align__(16) __half g_xph[(size_t)MAXN * DOUT];    // projected X, fp16
__device__ __align__(16) float g_G[DOUT * DOUT];               // gram -> chol L
__device__ __align__(16) __nv_bfloat16 g_wth[DOUT * DIN];      // W_ortho^T hi  [n][k]
__device__ __align__(16) __nv_bfloat16 g_wtl[DOUT * DIN];      // W_ortho^T lo  [n][k]
__device__ int   g_deg[MAXN];
__device__ int   g_rowptr[MAXN];
__device__ int   g_cursor[MAXN];
__device__ int   g_total;
__device__ __align__(8) int2 g_edge[MAXE];                     // .x=col .y=val bits

__device__ __forceinline__ uint32_t pack_bf16(__nv_bfloat16 a, __nv_bfloat16 b) {
    __nv_bfloat162 t(a, b);
    uint32_t r; memcpy(&r, &t, 4); return r;
}

__device__ __forceinline__ uint32_t smem_u32(const void* p) {
    return (uint32_t)__cvta_generic_to_shared(p);
}

// async 16B copy, L1-bypass
__device__ __forceinline__ void cp16(uint32_t s, const void* g) {
    asm volatile("cp.async.cg.shared.global [%0], [%1], 16;" :: "r"(s), "l"(g));
}
#define CP_COMMIT() asm volatile("cp.async.commit_group;")
#define CP_WAIT0()  asm volatile("cp.async.wait_group 0;")

// warp-level bf16 MMA (sm_80+; compiles on plain sm_100 target)
__device__ __forceinline__ void mma16816(float* d, const uint32_t* a, const uint32_t* b) {
    asm volatile("mma.sync.aligned.m16n8k16.row.col.f32.bf16.bf16.f32 "
        "{%0,%1,%2,%3}, {%4,%5,%6,%7}, {%8,%9}, {%0,%1,%2,%3};"
        : "+f"(d[0]), "+f"(d[1]), "+f"(d[2]), "+f"(d[3])
        : "r"(a[0]), "r"(a[1]), "r"(a[2]), "r"(a[3]), "r"(b[0]), "r"(b[1]));
}

__device__ __forceinline__ void ldm_x4(uint32_t* r, uint32_t addr) {
    asm volatile("ldmatrix.sync.aligned.m8n8.x4.shared.b16 {%0,%1,%2,%3}, [%4];"
        : "=r"(r[0]), "=r"(r[1]), "=r"(r[2]), "=r"(r[3]) : "r"(addr));
}

// XOR swizzle on 64B rows packed in 128B lines: bits[4:6] ^= bits[7:9]
__device__ __forceinline__ uint32_t swz(uint32_t off) {
    return off ^ ((off >> 3) & 0x70);
}

// ---------------- kA: Gram matrix + zero deg/total ---------------------------
__global__ void __launch_bounds__(128) kA(const float* __restrict__ W, int n) {
    if (blockIdx.x < DOUT) {
        __shared__ float col[DIN];
        int i = blockIdx.x, j = threadIdx.x;
        for (int k = j; k < DIN; k += DOUT) col[k] = W[k * DOUT + i];
        __syncthreads();
        float acc = 0.f;
        #pragma unroll 8
        for (int k = 0; k < DIN; k++) acc = fmaf(col[k], W[k * DOUT + j], acc);
        g_G[i * DOUT + j] = acc + (i == j ? 1e-4f : 0.f);
    } else {
        if (blockIdx.x == DOUT && threadIdx.x == 0) g_total = 0;
        int i = (blockIdx.x - DOUT) * 128 + threadIdx.x;
        if (i < n) g_deg[i] = 0;
    }
}

// ---------------- Cholesky: 512 threads, 4 per row, pitch-129 smem ----------
static constexpr int CP_ = 129;
static constexpr int CHOL_SMEM = (DOUT * CP_ + DOUT) * 4;   // 66560 B

__global__ void __launch_bounds__(512) k_chol() {
    extern __shared__ float s[];
    float* diag = s + DOUT * CP_;
    int tid = threadIdx.x;
    int t = tid >> 2;        // row 0..127
    int q = tid & 3;         // column-quarter within row
    for (int idx = tid; idx < DOUT * DOUT; idx += 512) {
        int r = idx >> 7, c = idx & 127;
        s[r * CP_ + c] = g_G[idx];
    }
    __syncthreads();
    for (int k = 0; k < DOUT; k++) {
        float dk = sqrtf(s[k * CP_ + k]);
        if (tid == 0) diag[k] = dk;
        if (q == 0 && t > k) s[t * CP_ + k] /= dk;
        __syncthreads();
        if (t > k) {
            float lik = s[t * CP_ + k];
            for (int j = k + 1 + q; j <= t; j += 4)
                s[t * CP_ + j] -= lik * s[j * CP_ + k];
        }
        __syncthreads();
    }
    for (int idx = tid; idx < DOUT * DOUT; idx += 512) {
        int r = idx >> 7, c = idx & 127;
        g_G[idx] = (r == c) ? diag[r] : s[r * CP_ + c];
    }
}

// W_ortho row r solves L y = W[r,:]^T; store y^T bf16 hi/lo at [n=j][k=r].
__global__ void __launch_bounds__(128) k_ortho(const float* __restrict__ W) {
    extern __shared__ char s_raw[];
    float* Ls = (float*)s_raw;                // 128*128 floats
    float* ys = Ls + DOUT * DOUT;             // [j][thread]
    int t = threadIdx.x;
    for (int idx = t; idx < DOUT * DOUT; idx += 128) Ls[idx] = g_G[idx];
    __syncthreads();
    int r = blockIdx.x * 128 + t;             // 0..511 (k index)
    const float* wr = W + (size_t)r * DOUT;
    for (int j = 0; j < DOUT; j++) {
        float s0 = 0.f, s1 = 0.f, s2 = 0.f, s3 = 0.f;
        const float* lj = Ls + j * DOUT;
        int k = 0;
        for (; k + 3 < j; k += 4) {
            s0 = fmaf(lj[k],     ys[k * 128 + t],       s0);
            s1 = fmaf(lj[k + 1], ys[(k + 1) * 128 + t], s1);
            s2 = fmaf(lj[k + 2], ys[(k + 2) * 128 + t], s2);
            s3 = fmaf(lj[k + 3], ys[(k + 3) * 128 + t], s3);
        }
        for (; k < j; k++) s0 = fmaf(lj[k], ys[k * 128 + t], s0);
        float sv = (wr[j] - ((s0 + s1) + (s2 + s3))) / lj[j];
        ys[j * 128 + t] = sv;
        __nv_bfloat16 h = __float2bfloat16_rn(sv);
        float rem = sv - __bfloat162float(h);
        g_wth[j * DIN + r] = h;
        g_wtl[j * DIN + r] = __float2bfloat16_rn(rem);
    }
}

// ---------------- GEMM: Xp = X @ W_ortho  (mma.sync bf16 hi/lo split) -------
// CTA: 256 thr (8 warps), M=128, N=128, K chunks of 32, double-buffered,
// XOR-swizzled 64B rows, ldmatrix fragment loads, 2 CTAs/SM, fp16 output.
static constexpr int TILE_B  = 128 * 64;            // 8192
static constexpr int STAGE_B = 4 * TILE_B;          // 32768 (Ah, Al, Bh, Bl)
static constexpr int GEMM_SMEM = 2 * STAGE_B;       // 65536

__global__ void __launch_bounds__(256, 2)
k_gemm(const float* __restrict__ X, int nn) {
    extern __shared__ char smem[];
    uint32_t sm0 = smem_u32(smem);
    int tid  = threadIdx.x;
    int lane = tid & 31;
    int wid  = tid >> 5;
    int warpm = wid & 3;          // 4 tiles of 32 rows
    int warpn = wid >> 2;         // 2 tiles of 64 cols
    int m0 = blockIdx.x * 128;

    float d[2][8][4];
    #pragma unroll
    for (int mf = 0; mf < 2; mf++)
        #pragma unroll
        for (int nf = 0; nf < 8; nf++)
            #pragma unroll
            for (int q = 0; q < 4; q++) d[mf][nf][q] = 0.f;

    int srow[4], skq[4];
    #pragma unroll
    for (int t = 0; t < 4; t++) {
        int idx = tid + t * 256;
        srow[t] = idx >> 3;
        skq[t]  = (idx & 7) << 2;
    }
    int brow[2], bq[2];
    #pragma unroll
    for (int t = 0; t < 2; t++) {
        int idx = tid + t * 256;
        brow[t] = idx >> 2;
        bq[t]   = (idx & 3) * 16;
    }

    uint32_t aoff[2][2];  // [mf][ks]
    {
        int arow = warpm * 32 + ((lane >> 3) & 1) * 8 + (lane & 7);
        int akb  = (lane >> 4) << 4;
        #pragma unroll
        for (int mf = 0; mf < 2; mf++)
            #pragma unroll
            for (int ks = 0; ks < 2; ks++)
                aoff[mf][ks] = swz((uint32_t)((arow + mf * 16) * 64 + ks * 32 + akb));
    }
    uint32_t boff[4][2];  // [np][ks]
    {
        int bn  = warpn * 64 + ((lane >= 16) ? 8 : 0) + (lane & 7);
        int bkb = ((lane >> 3) & 1) * 16;
        #pragma unroll
        for (int np = 0; np < 4; np++)
            #pragma unroll
            for (int ks = 0; ks < 2; ks++)
                boff[np][ks] = swz((uint32_t)((bn + np * 16) * 64 + ks * 32 + bkb));
    }

    // ---- prologue: chunk 0 ----
    {
        uint32_t sBh = sm0 + 2 * TILE_B, sBl = sm0 + 3 * TILE_B;
        #pragma unroll
        for (int t = 0; t < 2; t++) {
            uint32_t off = swz((uint32_t)(brow[t] * 64 + bq[t]));
            cp16(sBh + off, (const char*)(g_wth + (size_t)brow[t] * DIN) + bq[t]);
            cp16(sBl + off, (const char*)(g_wtl + (size_t)brow[t] * DIN) + bq[t]);
        }
        CP_COMMIT();
        #pragma unroll
        for (int t = 0; t < 4; t++) {
            int row = srow[t], kq = skq[t];
            int m = m0 + row;
            float4 xv = make_float4(0.f, 0.f, 0.f, 0.f);
            if (m < nn) xv = *(const float4*)(X + (size_t)m * DIN + kq);
            __nv_bfloat16 h0 = __float2bfloat16_rn(xv.x), h1 = __float2bfloat16_rn(xv.y);
            __nv_bfloat16 h2 = __float2bfloat16_rn(xv.z), h3 = __float2bfloat16_rn(xv.w);
            uint2 hv; hv.x = pack_bf16(h0, h1); hv.y = pack_bf16(h2, h3);
            uint2 lv;
            lv.x = pack_bf16(__float2bfloat16_rn(xv.x - __bfloat162float(h0)),
                             __float2bfloat16_rn(xv.y - __bfloat162float(h1)));
            lv.y = pack_bf16(__float2bfloat16_rn(xv.z - __bfloat162float(h2)),
                             __float2bfloat16_rn(xv.w - __bfloat162float(h3)));
            uint32_t off = swz((uint32_t)(row * 64 + kq * 2));
            *(uint64_t*)(smem + off)          = *(uint64_t*)&hv;
            *(uint64_t*)(smem + TILE_B + off) = *(uint64_t*)&lv;
        }
        CP_WAIT0();
    }
    __syncthreads();

    #pragma unroll 1
    for (int c = 0; c < 16; c++) {
        int s = c & 1;
        float4 areg[4];
        if (c < 15) {
            int koff = (c + 1) * 32;
            uint32_t nst = sm0 + (uint32_t)(s ^ 1) * STAGE_B;
            #pragma unroll
            for (int t = 0; t < 2; t++) {
                uint32_t off = swz((uint32_t)(brow[t] * 64 + bq[t]));
                cp16(nst + 2 * TILE_B + off,
                     (const char*)(g_wth + (size_t)brow[t] * DIN + koff) + bq[t]);
                cp16(nst + 3 * TILE_B + off,
                     (const char*)(g_wtl + (size_t)brow[t] * DIN + koff) + bq[t]);
            }
            CP_COMMIT();
            #pragma unroll
            for (int t = 0; t < 4; t++) {
                int m = m0 + srow[t];
                areg[t] = make_float4(0.f, 0.f, 0.f, 0.f);
                if (m < nn) areg[t] = *(const float4*)(X + (size_t)m * DIN + koff + skq[t]);
            }
        }

        uint32_t stb = sm0 + (uint32_t)s * STAGE_B;
        #pragma unroll
        for (int ks = 0; ks < 2; ks++) {
            uint32_t ahf[2][4], alf[2][4];
            #pragma unroll
            for (int mf = 0; mf < 2; mf++) {
                ldm_x4(ahf[mf], stb + aoff[mf][ks]);
                ldm_x4(alf[mf], stb + TILE_B + aoff[mf][ks]);
            }
            #pragma unroll
            for (int np = 0; np < 4; np++) {
                uint32_t bh4[4], bl4[4];
                ldm_x4(bh4, stb + 2 * TILE_B + boff[np][ks]);
                ldm_x4(bl4, stb + 3 * TILE_B + boff[np][ks]);
                #pragma unroll
                for (int sub = 0; sub < 2; sub++) {
                    int nf = np * 2 + sub;
                    #pragma unroll
                    for (int mf = 0; mf < 2; mf++) {
                        mma16816(d[mf][nf], ahf[mf], bh4 + 2 * sub);
                        mma16816(d[mf][nf], ahf[mf], bl4 + 2 * sub);
                        mma16816(d[mf][nf], alf[mf], bh4 + 2 * sub);
                    }
                }
            }
        }

        if (c < 15) {
            char* st = smem + (size_t)(s ^ 1) * STAGE_B;
            #pragma unroll
            for (int t = 0; t < 4; t++) {
                int row = srow[t], kq = skq[t];
                float4 xv = areg[t];
                __nv_bfloat16 h0 = __float2bfloat16_rn(xv.x), h1 = __float2bfloat16_rn(xv.y);
                __nv_bfloat16 h2 = __float2bfloat16_rn(xv.z), h3 = __float2bfloat16_rn(xv.w);
                uint2 hv; hv.x = pack_bf16(h0, h1); hv.y = pack_bf16(h2, h3);
                uint2 lv;
                lv.x = pack_bf16(__float2bfloat16_rn(xv.x - __bfloat162float(h0)),
                                 __float2bfloat16_rn(xv.y - __bfloat162float(h1)));
                lv.y = pack_bf16(__float2bfloat16_rn(xv.z - __bfloat162float(h2)),
                                 __float2bfloat16_rn(xv.w - __bfloat162float(h3)));
                uint32_t off = swz((uint32_t)(row * 64 + kq * 2));
                *(uint64_t*)(st + off)          = *(uint64_t*)&hv;
                *(uint64_t*)(st + TILE_B + off) = *(uint64_t*)&lv;
            }
        }
        CP_WAIT0();
        __syncthreads();
    }

    // ---- epilogue: write Xp as fp16 ----
    int qrow = lane >> 2;
    #pragma unroll
    for (int mf = 0; mf < 2; mf++) {
        int r0 = m0 + warpm * 32 + mf * 16 + qrow;
        #pragma unroll
        for (int nf = 0; nf < 8; nf++) {
            int col = warpn * 64 + nf * 8 + (lane & 3) * 2;
            if (r0 < nn)
                *(__half2*)(g_xph + (size_t)r0 * DOUT + col) =
                    __floats2half2_rn(d[mf][nf][0], d[mf][nf][1]);
            if (r0 + 8 < nn)
                *(__half2*)(g_xph + (size_t)(r0 + 8) * DOUT + col) =
                    __floats2half2_rn(d[mf][nf][2], d[mf][nf][3]);
        }
    }
}

// ---------------- CSR build --------------------------------------------------
__global__ void k_hist(const int* __restrict__ rows, int ne) {
    int i = blockIdx.x * blockDim.x + threadIdx.x;
    int b = i * 4;
    if (b + 3 < ne) {
        int4 r = *(const int4*)(rows + b);
        atomicAdd(&g_deg[r.x], 1);
        atomicAdd(&g_deg[r.y], 1);
        atomicAdd(&g_deg[r.z], 1);
        atomicAdd(&g_deg[r.w], 1);
    } else {
        for (int e = b; e < ne; e++) atomicAdd(&g_deg[rows[e]], 1);
    }
}

// row-base allocation: warp-aggregated atomic; seeds cursor with the base
__global__ void k_alloc(int n) {
    int i = blockIdx.x * blockDim.x + threadIdx.x;
    int lane = threadIdx.x & 31;
    int d = (i < n) ? g_deg[i] : 0;
    int incl = d;
    #pragma unroll
    for (int o = 1; o < 32; o <<= 1) {
        int v = __shfl_up_sync(0xffffffffu, incl, o);
        if (lane >= o) incl += v;
    }
    int wsum = __shfl_sync(0xffffffffu, incl, 31);
    int base = 0;
    if (lane == 31 && wsum > 0) base = atomicAdd(&g_total, wsum);
    base = __shfl_sync(0xffffffffu, base, 31);
    if (i < n) {
        int rp = base + incl - d;
        g_rowptr[i] = rp;
        g_cursor[i] = rp;   // scatter allocates directly from cursor
    }
}

__global__ void k_scatter(const int* __restrict__ rows, const int* __restrict__ cols,
                          const float* __restrict__ vals, int ne) {
    int i = blockIdx.x * blockDim.x + threadIdx.x;
    int b = i * 4;
    if (b + 3 < ne) {
        int4   r = *(const int4*)(rows + b);
        int4   c = *(const int4*)(cols + b);
        float4 v = *(const float4*)(vals + b);
        int p0 = atomicAdd(&g_cursor[r.x], 1);
        g_edge[p0] = make_int2(c.x, __float_as_int(v.x));
        int p1 = atomicAdd(&g_cursor[r.y], 1);
        g_edge[p1] = make_int2(c.y, __float_as_int(v.y));
        int p2 = atomicAdd(&g_cursor[r.z], 1);
        g_edge[p2] = make_int2(c.z, __float_as_int(v.z));
        int p3 = atomicAdd(&g_cursor[r.w], 1);
        g_edge[p3] = make_int2(c.w, __float_as_int(v.w));
    } else {
        for (int e = b; e < ne; e++) {
            int pos = atomicAdd(&g_cursor[rows[e]], 1);
            g_edge[pos] = make_int2(cols[e], __float_as_int(vals[e]));
        }
    }
}

// ---------------- SpMM + tanh: warp per destination row, fp16 gathers -------
__global__ void __launch_bounds__(256) k_spmm(float* __restrict__ out, int n) {
    int warp = (blockIdx.x * blockDim.x + threadIdx.x) >> 5;
    int lane = threadIdx.x & 31;
    if (warp >= n) return;
    int beg = g_rowptr[warp];
    int end = beg + g_deg[warp];
    const __half* xpb = g_xph + lane * 4;
    float4 acc = make_float4(0.f, 0.f, 0.f, 0.f);
    for (int b = beg; b < end; b += 32) {
        int idx = b + lane;
        int cc = 0; float vv = 0.f;
        if (idx < end) {
            int2 e = __ldg(&g_edge[idx]);
            cc = e.x; vv = __int_as_float(e.y);
        }
        int cnt = min(32, end - b);
        int cnt4 = (cnt + 3) & ~3;
        for (int j = 0; j < cnt4; j += 4) {
            int   c0 = __shfl_sync(0xffffffffu, cc, j);
            int   c1 = __shfl_sync(0xffffffffu, cc, j + 1);
            int   c2 = __shfl_sync(0xffffffffu, cc, j + 2);
            int   c3 = __shfl_sync(0xffffffffu, cc, j + 3);
            float v0 = __shfl_sync(0xffffffffu, vv, j);
            float v1 = __shfl_sync(0xffffffffu, vv, j + 1);
            float v2 = __shfl_sync(0xffffffffu, vv, j + 2);
            float v3 = __shfl_sync(0xffffffffu, vv, j + 3);
            uint2 h0 = __ldg((const uint2*)(xpb + (size_t)c0 * DOUT));
            uint2 h1 = __ldg((const uint2*)(xpb + (size_t)c1 * DOUT));
            uint2 h2 = __ldg((const uint2*)(xpb + (size_t)c2 * DOUT));
            uint2 h3 = __ldg((const uint2*)(xpb + (size_t)c3 * DOUT));
            float2 a0 = __half22float2(*(__half2*)&h0.x), b0 = __half22float2(*(__half2*)&h0.y);
            float2 a1 = __half22float2(*(__half2*)&h1.x), b1 = __half22float2(*(__half2*)&h1.y);
            float2 a2 = __half22float2(*(__half2*)&h2.x), b2 = __half22float2(*(__half2*)&h2.y);
            float2 a3 = __half22float2(*(__half2*)&h3.x), b3 = __half22float2(*(__half2*)&h3.y);
            acc.x = fmaf(v0, a0.x, acc.x); acc.y = fmaf(v0, a0.y, acc.y);
            acc.z = fmaf(v0, b0.x, acc.z); acc.w = fmaf(v0, b0.y, acc.w);
            acc.x = fmaf(v1, a1.x, acc.x); acc.y = fmaf(v1, a1.y, acc.y);
            acc.z = fmaf(v1, b1.x, acc.z); acc.w = fmaf(v1, b1.y, acc.w);
            acc.x = fmaf(v2, a2.x, acc.x); acc.y = fmaf(v2, a2.y, acc.y);
            acc.z = fmaf(v2, b2.x, acc.z); acc.w = fmaf(v2, b2.y, acc.w);
            acc.x = fmaf(v3, a3.x, acc.x); acc.y = fmaf(v3, a3.y, acc.y);
            acc.z = fmaf(v3, b3.x, acc.z); acc.w = fmaf(v3, b3.y, acc.w);
        }
    }
    float4 o;
    o.x = tanhf(acc.x); o.y = tanhf(acc.y);
    o.z = tanhf(acc.z); o.w = tanhf(acc.w);
    *(float4*)(out + (size_t)warp * DOUT + lane * 4) = o;
}

// ---------------- launch -----------------------------------------------------
extern "C" void kernel_launch(void* const* d_in, const int* in_sizes, int n_in,
                              void* d_out, int out_size) {
    const float* X    = (const float*)d_in[0];   // [N, 512]
    const float* W    = (const float*)d_in[1];   // [512, 128]
    const float* vals = (const float*)d_in[2];   // [E]
    const int*   rows = (const int*)d_in[3];     // [E]
    const int*   cols = (const int*)d_in[4];     // [E]
    float* out = (float*)d_out;

    int nn = in_sizes[0] / DIN;
    int ne = in_sizes[2];

    cudaFuncSetAttribute(k_chol,  cudaFuncAttributeMaxDynamicSharedMemorySize, CHOL_SMEM);
    cudaFuncSetAttribute(k_ortho, cudaFuncAttributeMaxDynamicSharedMemorySize, 131072);
    cudaFuncSetAttribute(k_gemm,  cudaFuncAttributeMaxDynamicSharedMemorySize, GEMM_SMEM);

    int zblocks = (nn + 127) / 128;
    int e4 = (ne + 3) / 4;

    // ncu lands on launch index 3 -> k_scatter profiled this round
    kA<<<DOUT + zblocks, 128>>>(W, nn);                          // 0: gram + zeroing
    k_hist<<<(e4 + 255) / 256, 256>>>(rows, ne);                 // 1
    k_alloc<<<(nn + 255) / 256, 256>>>(nn);                      // 2
    k_scatter<<<(e4 + 255) / 256, 256>>>(rows, cols, vals, ne);  // 3  <- profiled
    k_chol<<<1, 512, CHOL_SMEM>>>();                             // 4
    k_ortho<<<DIN / 128, 128, 131072>>>(W);                      // 5
    k_gemm<<<(nn + 127) / 128, 256, GEMM_SMEM>>>(X, nn);         // 6
    k_spmm<<<(nn * 32 + 255) / 256, 256>>>(out, nn);             // 7
}